// round 9
// baseline (speedup 1.0000x reference)
#include <cuda_runtime.h>
#include <cuda_bf16.h>
#include <cstdint>
#include <cstddef>

#define BATCH 4
#define SEQ   2048
#define EMB   1024
#define NH    16
#define HD    64
#define MTOT  (BATCH * SEQ)        /* 8192 */
#define KSPLIT (3 * EMB)           /* 3072: W-side 3-block */
#define KA2   (2 * EMB)            /* 2048: A-side 2-block [hi|lo] */
#define BK    32
#define NITER (KSPLIT / BK)        /* 96 */
#define LOG2E 1.44269504f
#define NEG_BIG (-1e30f)
#define BHS   ((size_t)BATCH * NH * SEQ)   /* 131072 per-head rows */

// ---------------- scratch (__device__ globals; no allocs) -------------------
__device__ __align__(1024) __nv_bfloat16 g_a2[3][(size_t)MTOT * KA2];   // 3x32MB
__device__ __align__(1024) __nv_bfloat16 g_w3[4][(size_t)EMB * KSPLIT]; // 4x6MB
__device__ __align__(1024) __nv_bfloat16 g_q2[BHS * 128];  // [b,h,s][hi|lo] 32MB
__device__ __align__(1024) __nv_bfloat16 g_k2[BHS * 128];  // 32MB
__device__ __align__(1024) __nv_bfloat16 g_vh[BHS * HD];   // 16MB
__device__ __align__(1024) __nv_bfloat16 g_vl[BHS * HD];   // 16MB

// ---------------- PTX helpers (baseline ISA: sm_80-era ops) -----------------
__device__ __forceinline__ uint32_t smem_u32(const void* p) {
    uint32_t a;
    asm("{ .reg .u64 t; cvta.to.shared.u64 t, %1; cvt.u32.u64 %0, t; }" : "=r"(a) : "l"(p));
    return a;
}
#define CP_ASYNC16(dst, src) \
    asm volatile("cp.async.cg.shared.global [%0], [%1], 16;" :: "r"(dst), "l"(src) : "memory")
#define CP_COMMIT() asm volatile("cp.async.commit_group;" ::: "memory")
#define CP_WAIT1()  asm volatile("cp.async.wait_group 1;" ::: "memory")

__device__ __forceinline__ void ldsm4(uint32_t (&r)[4], uint32_t addr) {
    asm volatile("ldmatrix.sync.aligned.m8n8.x4.shared.b16 {%0,%1,%2,%3}, [%4];"
                 : "=r"(r[0]), "=r"(r[1]), "=r"(r[2]), "=r"(r[3]) : "r"(addr));
}
__device__ __forceinline__ void ldsm4t(uint32_t (&r)[4], uint32_t addr) {
    asm volatile("ldmatrix.sync.aligned.m8n8.x4.trans.shared.b16 {%0,%1,%2,%3}, [%4];"
                 : "=r"(r[0]), "=r"(r[1]), "=r"(r[2]), "=r"(r[3]) : "r"(addr));
}
__device__ __forceinline__ void mma16816(float (&d)[4], const uint32_t (&a)[4],
                                         uint32_t b0, uint32_t b1) {
    asm volatile(
        "mma.sync.aligned.m16n8k16.row.col.f32.bf16.bf16.f32 "
        "{%0,%1,%2,%3}, {%4,%5,%6,%7}, {%8,%9}, {%0,%1,%2,%3};"
        : "+f"(d[0]), "+f"(d[1]), "+f"(d[2]), "+f"(d[3])
        : "r"(a[0]), "r"(a[1]), "r"(a[2]), "r"(a[3]), "r"(b0), "r"(b1));
}
__device__ __forceinline__ uint32_t pk2(__nv_bfloat16 a, __nv_bfloat16 b) {
    __nv_bfloat162 t = __halves2bfloat162(a, b);
    return *reinterpret_cast<uint32_t*>(&t);
}
__device__ __forceinline__ void split1(float v, __nv_bfloat16& h, __nv_bfloat16& l) {
    h = __float2bfloat16(v);
    l = __float2bfloat16(v - __bfloat162float(h));
}

// ---------------------------------------------------------------------------
// split_all (one launch): z<4 -> weights [hi|hi|lo]; z>=4 -> activations [hi|lo]
// ---------------------------------------------------------------------------
__global__ __launch_bounds__(256)
void split_all(const float* __restrict__ q, const float* __restrict__ k,
               const float* __restrict__ v,
               const float* __restrict__ wq, const float* __restrict__ wk,
               const float* __restrict__ wv, const float* __restrict__ wo,
               __nv_bfloat16* __restrict__ a2, __nv_bfloat16* __restrict__ w3)
{
    const int z = blockIdx.y;
    if (z < 4) {
        const float* X = (z == 0) ? wq : (z == 1) ? wk : (z == 2) ? wv : wo;
        __nv_bfloat16* Y = w3 + (size_t)z * EMB * KSPLIT;
        size_t idx = (size_t)blockIdx.x * 256 + threadIdx.x;
        size_t row = idx >> 8;
        int    c   = (int)(idx & 255) << 2;
        float4 x = ((const float4*)X)[idx];
        __nv_bfloat16 h0, h1, h2, h3, l0, l1, l2, l3;
        split1(x.x, h0, l0); split1(x.y, h1, l1);
        split1(x.z, h2, l2); split1(x.w, h3, l3);
        uint2 hv = make_uint2(pk2(h0, h1), pk2(h2, h3));
        uint2 lv = make_uint2(pk2(l0, l1), pk2(l2, l3));
        size_t base = row * (size_t)KSPLIT + c;
        *(uint2*)(Y + base)        = hv;          // hi
        *(uint2*)(Y + base + 1024) = hv;          // hi (2nd block)
        *(uint2*)(Y + base + 2048) = lv;          // lo
    } else {
        const float* X = (z == 4) ? q : (z == 5) ? k : v;
        __nv_bfloat16* Y = a2 + (size_t)(z - 4) * MTOT * KA2;
        #pragma unroll
        for (int t = 0; t < 8; t++) {
            size_t idx = ((size_t)blockIdx.x * 8 + t) * 256 + threadIdx.x;
            size_t row = idx >> 8;
            int    c   = (int)(idx & 255) << 2;
            float4 x = ((const float4*)X)[idx];
            __nv_bfloat16 h0, h1, h2, h3, l0, l1, l2, l3;
            split1(x.x, h0, l0); split1(x.y, h1, l1);
            split1(x.z, h2, l2); split1(x.w, h3, l3);
            size_t base = row * (size_t)KA2 + c;
            *(uint2*)(Y + base)        = make_uint2(pk2(h0, h1), pk2(h2, h3));
            *(uint2*)(Y + base + 1024) = make_uint2(pk2(l0, l1), pk2(l2, l3));
        }
    }
}

// ---------------------------------------------------------------------------
// GEMM core: C = A2[*,2048(LUT->3072)] @ W3[*,3072]^T + bias
// 6-stage cp.async pipeline in pairs, 1 barrier / 2 k-iters.
// Warp-staggered traversal: odd warps reverse half & ks order to decorrelate
// ldsm bursts from MMA bursts across the SM.
// ---------------------------------------------------------------------------
__device__ __forceinline__ int koffA(int it) { return (it < 64 ? it : it - 64) * BK; }

__device__ __forceinline__ void gemm_core(
    const __nv_bfloat16* __restrict__ A, const __nv_bfloat16* __restrict__ W,
    const float* __restrict__ bias, float* __restrict__ Cf,
    __nv_bfloat16* __restrict__ OH, __nv_bfloat16* __restrict__ OL,
    int mode, float scale, int m0, int n0, char* smem_raw)
{
    const uint32_t sbase = smem_u32(smem_raw);

    const int tid  = threadIdx.x;
    const int lane = tid & 31;
    const int wid  = tid >> 5;
    const int wm   = wid >> 2;
    const int wn   = wid & 3;
    const int hflip = wid & 1;           // stagger: half order
    const int kflip = (wid >> 1) & 1;    // stagger: ks order

    const __nv_bfloat16* Ap = A + (size_t)m0 * KA2;
    const __nv_bfloat16* Wp = W + (size_t)n0 * KSPLIT;

    const int lrow = tid >> 2;
    const int lc   = tid & 3;

    const int arow  = wm * 64 + (lane & 15);
    const int akh   = lane >> 4;
    const int aswz  = (arow >> 1) & 3;
    const int brow  = wn * 32 + (lane & 7) + ((lane & 16) ? 8 : 0);
    const int bkh   = (lane >> 3) & 1;
    const int bswz  = (brow >> 1) & 3;

    float acc[4][4][4];
    #pragma unroll
    for (int i = 0; i < 4; i++)
        #pragma unroll
        for (int j = 0; j < 4; j++)
            #pragma unroll
            for (int k = 0; k < 4; k++) acc[i][j][k] = 0.f;

    // prologue: stages 0..3 as 2 committed pairs
    #pragma unroll
    for (int s = 0; s < 4; s++) {
        uint32_t sA = sbase + s * 16384;
        uint32_t sB = sA + 8192;
        const __nv_bfloat16* ag = Ap + koffA(s) + lc * 8;
        const __nv_bfloat16* wg = Wp + (size_t)s * BK + lc * 8;
        #pragma unroll
        for (int h = 0; h < 2; h++) {
            int r  = lrow + h * 64;
            int cs = lc ^ ((r >> 1) & 3);
            CP_ASYNC16(sA + r * 64 + cs * 16, ag + (size_t)r * KA2);
            CP_ASYNC16(sB + r * 64 + cs * 16, wg + (size_t)r * KSPLIT);
        }
        if (s & 1) CP_COMMIT();
    }

    int st = 0;
    for (int j = 0; j < NITER / 2; j++) {
        CP_WAIT1();
        __syncthreads();

        #pragma unroll
        for (int h2 = 0; h2 < 2; h2++) {
            const int half = h2 ^ hflip;
            const uint32_t sA = sbase + (st + half) * 16384;
            const uint32_t sB = sA + 8192;
            #pragma unroll
            for (int ks2 = 0; ks2 < 2; ks2++) {
                const int ks = ks2 ^ kflip;
                uint32_t a[4][4];
                uint32_t b[4][2];
                const int ac = ((ks * 2 + akh) ^ aswz) * 16;
                const int bc = ((ks * 2 + bkh) ^ bswz) * 16;
                #pragma unroll
                for (int mi = 0; mi < 4; mi++)
                    ldsm4(a[mi], sA + (arow + mi * 16) * 64 + ac);
                #pragma unroll
                for (int nj = 0; nj < 2; nj++) {
                    uint32_t t4[4];
                    ldsm4(t4, sB + (brow + nj * 16) * 64 + bc);
                    b[nj * 2][0]     = t4[0]; b[nj * 2][1]     = t4[1];
                    b[nj * 2 + 1][0] = t4[2]; b[nj * 2 + 1][1] = t4[3];
                }
                #pragma unroll
                for (int mi = 0; mi < 4; mi++)
                    #pragma unroll
                    for (int ni = 0; ni < 4; ni++)
                        mma16816(acc[mi][ni], a[mi], b[ni][0], b[ni][1]);
            }
        }

        const int it0 = 2 * j + 4;
        if (it0 < NITER) {
            int pf = st + 4; if (pf >= 6) pf -= 6;
            #pragma unroll
            for (int half = 0; half < 2; half++) {
                const uint32_t dA = sbase + (pf + half) * 16384;
                const uint32_t dB = dA + 8192;
                const __nv_bfloat16* ag = Ap + koffA(it0 + half) + lc * 8;
                const __nv_bfloat16* wg = Wp + (size_t)(it0 + half) * BK + lc * 8;
                #pragma unroll
                for (int h = 0; h < 2; h++) {
                    int r  = lrow + h * 64;
                    int cs = lc ^ ((r >> 1) & 3);
                    CP_ASYNC16(dA + r * 64 + cs * 16, ag + (size_t)r * KA2);
                    CP_ASYNC16(dB + r * 64 + cs * 16, wg + (size_t)r * KSPLIT);
                }
            }
        }
        CP_COMMIT();
        st += 2; if (st >= 6) st -= 6;
    }

    // ---- epilogue ----
    const int trow = lane >> 2;
    const int tcol = (lane & 3) * 2;
    #pragma unroll
    for (int mi = 0; mi < 4; mi++) {
        const int row = m0 + wm * 64 + mi * 16 + trow;
        #pragma unroll
        for (int ni = 0; ni < 4; ni++) {
            const int col = n0 + wn * 32 + ni * 8 + tcol;
            const float b0 = __ldg(bias + col), b1 = __ldg(bias + col + 1);
            float v00 = acc[mi][ni][0] + b0, v01 = acc[mi][ni][1] + b1;
            float v10 = acc[mi][ni][2] + b0, v11 = acc[mi][ni][3] + b1;
            if (mode == 0) {
                *(float2*)(Cf + (size_t)row * EMB + col)       = make_float2(v00, v01);
                *(float2*)(Cf + (size_t)(row + 8) * EMB + col) = make_float2(v10, v11);
            } else {
                v00 *= scale; v01 *= scale; v10 *= scale; v11 *= scale;
                const int hh = col >> 6, d = col & 63;
                const size_t drow = ((size_t)((row >> 11) * NH + hh)) * SEQ + (row & 2047);
                __nv_bfloat16 h0, h1, h2, h3, l0, l1, l2, l3;
                split1(v00, h0, l0); split1(v01, h1, l1);
                split1(v10, h2, l2); split1(v11, h3, l3);
                if (mode == 3) {
                    *(uint32_t*)(OH + drow * HD + d)       = pk2(h0, h1);
                    *(uint32_t*)(OH + (drow + 8) * HD + d) = pk2(h2, h3);
                    *(uint32_t*)(OL + drow * HD + d)       = pk2(l0, l1);
                    *(uint32_t*)(OL + (drow + 8) * HD + d) = pk2(l2, l3);
                } else {
                    __nv_bfloat16* p0 = OH + drow * 128 + d;
                    __nv_bfloat16* p1 = OH + (drow + 8) * 128 + d;
                    *(uint32_t*)(p0)      = pk2(h0, h1);
                    *(uint32_t*)(p0 + 64) = pk2(l0, l1);
                    *(uint32_t*)(p1)      = pk2(h2, h3);
                    *(uint32_t*)(p1 + 64) = pk2(l2, l3);
                }
            }
        }
    }
}

// z-batched QKV projections: z=0 -> q2 (scaled), z=1 -> k2, z=2 -> vh/vl
__global__ __launch_bounds__(256, 2)
void gemm_qkv(const __nv_bfloat16* __restrict__ Abase,
              const __nv_bfloat16* __restrict__ Wbase,
              const float* __restrict__ bq, const float* __restrict__ bk,
              const float* __restrict__ bv,
              __nv_bfloat16* __restrict__ q2, __nv_bfloat16* __restrict__ k2,
              __nv_bfloat16* __restrict__ vh, __nv_bfloat16* __restrict__ vl)
{
    extern __shared__ __align__(1024) char smem_raw[];
    const int z = blockIdx.z;
    const __nv_bfloat16* A = Abase + (size_t)z * MTOT * KA2;
    const __nv_bfloat16* W = Wbase + (size_t)z * EMB * KSPLIT;
    const float* bias = (z == 0) ? bq : (z == 1) ? bk : bv;
    __nv_bfloat16* OH = (z == 0) ? q2 : (z == 1) ? k2 : vh;
    __nv_bfloat16* OL = (z == 2) ? vl : nullptr;
    const float scale = (z == 0) ? 0.125f : 1.0f;
    gemm_core(A, W, bias, nullptr, OH, OL, z + 1, scale,
              blockIdx.y * 128, blockIdx.x * 128, smem_raw);
}

// out projection -> fp32 d_out
__global__ __launch_bounds__(256, 2)
void gemm_out(const __nv_bfloat16* __restrict__ A, const __nv_bfloat16* __restrict__ W,
              const float* __restrict__ bias, float* __restrict__ Cf)
{
    extern __shared__ __align__(1024) char smem_raw[];
    gemm_core(A, W, bias, Cf, nullptr, nullptr, 0, 1.0f,
              blockIdx.y * 128, blockIdx.x * 128, smem_raw);
}

// ---------------------------------------------------------------------------
// HMMA flash attention (causal), bf16 3-term via 2-block [hi|lo] operands.
// Warp-staggered QK slab order and PV chunk order.
// ---------------------------------------------------------------------------
__global__ __launch_bounds__(256, 2)
void attn_hmma(const __nv_bfloat16* __restrict__ Q2, const __nv_bfloat16* __restrict__ K2,
               const __nv_bfloat16* __restrict__ VH, const __nv_bfloat16* __restrict__ VL,
               __nv_bfloat16* __restrict__ A2)
{
    extern __shared__ __align__(1024) char smr[];
    const uint32_t sb = smem_u32(smr);
    const uint32_t QS = sb;                 // 4 slabs * 8192B
    const uint32_t KS = sb + 32768;         // 2 stages * 16384
    const uint32_t VS = sb + 65536;         // 2 stages * 16384

    const int tid  = threadIdx.x;
    const int lane = tid & 31;
    const int wid  = tid >> 5;
    const int bx   = gridDim.x - 1 - blockIdx.x;   // LPT: heavy first
    const int head = blockIdx.y;
    const int bz   = blockIdx.z;
    const int qb0  = bx * 128;
    const size_t bh = (size_t)(bz * NH + head);
    const int nkb  = 2 * bx + 2;

    const __nv_bfloat16* Qp = Q2 + (bh * SEQ + qb0) * 128;
    const __nv_bfloat16* Kp = K2 + bh * SEQ * 128;
    const __nv_bfloat16* VHp = VH + bh * SEQ * HD;
    const __nv_bfloat16* VLp = VL + bh * SEQ * HD;

    {
        const int r1 = tid >> 2, lc = tid & 3;
        #pragma unroll
        for (int kc = 0; kc < 4; kc++)
            #pragma unroll
            for (int h = 0; h < 2; h++) {
                int r = r1 + h * 64;
                int cs = lc ^ ((r >> 1) & 3);
                CP_ASYNC16(QS + kc * 8192 + r * 64 + cs * 16,
                           Qp + (size_t)r * 128 + kc * 32 + lc * 8);
            }
        int cs = lc ^ ((r1 >> 1) & 3);
        #pragma unroll
        for (int kc = 0; kc < 4; kc++)
            CP_ASYNC16(KS + kc * 4096 + r1 * 64 + cs * 16,
                       Kp + (size_t)r1 * 128 + kc * 32 + lc * 8);
        const int vr = tid >> 3, vc = tid & 7;
        #pragma unroll
        for (int h = 0; h < 2; h++) {
            int r = vr + h * 32;
            int pc = vc ^ (r & 7);
            CP_ASYNC16(VS + r * 128 + pc * 16, VHp + (size_t)r * HD + vc * 8);
            CP_ASYNC16(VS + 8192 + r * 128 + pc * 16, VLp + (size_t)r * HD + vc * 8);
        }
        CP_COMMIT();
    }

    const int arow = wid * 16 + (lane & 15);
    const int akh  = lane >> 4;
    const int aswz = (arow >> 1) & 3;
    const int brow = (lane & 7) + ((lane & 16) ? 8 : 0);
    const int bkh  = (lane >> 3) & 1;
    const int bswz = (brow >> 1) & 3;
    const int vrow = (lane & 7) + 8 * ((lane >> 3) & 1);
    const int vchb = lane >> 4;
    const int vswz = lane & 7;
    const int wrev = wid & 1;               // stagger flag

    float of[8][4];
    #pragma unroll
    for (int i = 0; i < 8; i++)
        #pragma unroll
        for (int j = 0; j < 4; j++) of[i][j] = 0.f;
    float mq[2] = { NEG_BIG, NEG_BIG };
    float lq[2] = { 0.f, 0.f };

    const int qrow0 = qb0 + wid * 16 + (lane >> 2);

    for (int kb = 0; kb < nkb; kb++) {
        const int st = kb & 1;
        const int kbase = kb * 64;

        if (kb + 1 < nkb) {
            const int nb = (kb + 1) * 64;
            const int s2 = st ^ 1;
            const int r1 = tid >> 2, lc = tid & 3;
            int cs = lc ^ ((r1 >> 1) & 3);
            #pragma unroll
            for (int kc = 0; kc < 4; kc++)
                CP_ASYNC16(KS + s2 * 16384 + kc * 4096 + r1 * 64 + cs * 16,
                           Kp + (size_t)(nb + r1) * 128 + kc * 32 + lc * 8);
            const int vr = tid >> 3, vc = tid & 7;
            #pragma unroll
            for (int h = 0; h < 2; h++) {
                int r = vr + h * 32;
                int pc = vc ^ (r & 7);
                CP_ASYNC16(VS + s2 * 16384 + r * 128 + pc * 16,
                           VHp + (size_t)(nb + r) * HD + vc * 8);
                CP_ASYNC16(VS + s2 * 16384 + 8192 + r * 128 + pc * 16,
                           VLp + (size_t)(nb + r) * HD + vc * 8);
            }
        }
        CP_COMMIT();
        CP_WAIT1();
        __syncthreads();

        float sf[8][4];
        #pragma unroll
        for (int i = 0; i < 8; i++)
            #pragma unroll
            for (int j = 0; j < 4; j++) sf[i][j] = 0.f;

        const uint32_t Kst = KS + st * 16384;
        const int qsel[6] = { 0, 1, 2, 3, 0, 1 };
        const int ksel[6] = { 0, 1, 0, 1, 2, 3 };
        #pragma unroll
        for (int t2 = 0; t2 < 6; t2++) {
            const int t = wrev ? 5 - t2 : t2;   // staggered slab order
            #pragma unroll
            for (int ks = 0; ks < 2; ks++) {
                uint32_t a[4];
                ldsm4(a, QS + qsel[t] * 8192 + arow * 64 + (((ks * 2 + akh) ^ aswz) * 16));
                const int bc = ((ks * 2 + bkh) ^ bswz) * 16;
                #pragma unroll
                for (int np = 0; np < 4; np++) {
                    uint32_t t4[4];
                    ldsm4(t4, Kst + ksel[t] * 4096 + (np * 16 + brow) * 64 + bc);
                    mma16816(sf[2 * np],     a, t4[0], t4[1]);
                    mma16816(sf[2 * np + 1], a, t4[2], t4[3]);
                }
            }
        }

        if (kb >= nkb - 2) {
            #pragma unroll
            for (int nt = 0; nt < 8; nt++) {
                int col = kbase + nt * 8 + 2 * (lane & 3);
                if (col     > qrow0)     sf[nt][0] = NEG_BIG;
                if (col + 1 > qrow0)     sf[nt][1] = NEG_BIG;
                if (col     > qrow0 + 8) sf[nt][2] = NEG_BIG;
                if (col + 1 > qrow0 + 8) sf[nt][3] = NEG_BIG;
            }
        }

        #pragma unroll
        for (int h = 0; h < 2; h++) {
            float mloc = NEG_BIG;
            #pragma unroll
            for (int nt = 0; nt < 8; nt++)
                mloc = fmaxf(mloc, fmaxf(sf[nt][2 * h], sf[nt][2 * h + 1]));
            mloc = fmaxf(mloc, __shfl_xor_sync(0xffffffffu, mloc, 1));
            mloc = fmaxf(mloc, __shfl_xor_sync(0xffffffffu, mloc, 2));
            float mnew = fmaxf(mq[h], mloc);
            float corr = exp2f((mq[h] - mnew) * LOG2E);
            mq[h] = mnew;
            lq[h] *= corr;
            float ps = 0.f;
            #pragma unroll
            for (int nt = 0; nt < 8; nt++) {
                float p0 = exp2f((sf[nt][2 * h] - mnew) * LOG2E);
                float p1 = exp2f((sf[nt][2 * h + 1] - mnew) * LOG2E);
                sf[nt][2 * h] = p0; sf[nt][2 * h + 1] = p1;
                ps += p0 + p1;
                of[nt][2 * h] *= corr; of[nt][2 * h + 1] *= corr;
            }
            ps += __shfl_xor_sync(0xffffffffu, ps, 1);
            ps += __shfl_xor_sync(0xffffffffu, ps, 2);
            lq[h] += ps;
        }

        const uint32_t Vst = VS + st * 16384;
        #pragma unroll
        for (int k2i = 0; k2i < 4; k2i++) {
            const int kc2 = wrev ? 3 - k2i : k2i;   // staggered chunk order
            const int j0 = 2 * kc2, j1 = j0 + 1;
            uint32_t ph[4], pl[4];
            #pragma unroll
            for (int q = 0; q < 4; q++) {
                const float p0 = (q & 2) ? sf[j1][(q & 1) * 2]     : sf[j0][(q & 1) * 2];
                const float p1 = (q & 2) ? sf[j1][(q & 1) * 2 + 1] : sf[j0][(q & 1) * 2 + 1];
                __nv_bfloat16 h0, h1, l0, l1;
                split1(p0, h0, l0); split1(p1, h1, l1);
                ph[q] = pk2(h0, h1);
                pl[q] = pk2(l0, l1);
            }
            const uint32_t rowoff = (kc2 * 16 + vrow) * 128;
            #pragma unroll
            for (int np = 0; np < 4; np++) {
                const int pc = (2 * np + vchb) ^ vswz;
                uint32_t bh4[4], bl4[4];
                ldsm4t(bh4, Vst + rowoff + pc * 16);
                ldsm4t(bl4, Vst + 8192 + rowoff + pc * 16);
                mma16816(of[2 * np],     ph, bh4[0], bh4[1]);
                mma16816(of[2 * np + 1], ph, bh4[2], bh4[3]);
                mma16816(of[2 * np],     pl, bh4[0], bh4[1]);
                mma16816(of[2 * np + 1], pl, bh4[2], bh4[3]);
                mma16816(of[2 * np],     ph, bl4[0], bl4[1]);
                mma16816(of[2 * np + 1], ph, bl4[2], bl4[3]);
            }
        }
        __syncthreads();
    }

    const float inv0 = 1.f / lq[0];
    const float inv1 = 1.f / lq[1];
    const size_t ar0 = (size_t)bz * SEQ + qb0 + wid * 16 + (lane >> 2);
    const size_t ar1 = ar0 + 8;
    const int colb = head * 64 + 2 * (lane & 3);
    #pragma unroll
    for (int nt = 0; nt < 8; nt++) {
        int col = colb + nt * 8;
        float v0 = of[nt][0] * inv0, v1 = of[nt][1] * inv0;
        float v2 = of[nt][2] * inv1, v3 = of[nt][3] * inv1;
        __nv_bfloat16 h0, h1, h2, h3, l0, l1, l2, l3;
        split1(v0, h0, l0); split1(v1, h1, l1);
        split1(v2, h2, l2); split1(v3, h3, l3);
        __nv_bfloat16* d0 = A2 + ar0 * KA2 + col;
        __nv_bfloat16* d1 = A2 + ar1 * KA2 + col;
        *(uint32_t*)(d0)        = pk2(h0, h1);
        *(uint32_t*)(d0 + 1024) = pk2(l0, l1);
        *(uint32_t*)(d1)        = pk2(h2, h3);
        *(uint32_t*)(d1 + 1024) = pk2(l2, l3);
    }
}

// ---------------------------------------------------------------------------
extern "C" void kernel_launch(void* const* d_in, const int* in_sizes, int n_in,
                              void* d_out, int out_size)
{
    const float* query = (const float*)d_in[0];
    const float* key   = (const float*)d_in[1];
    const float* value = (const float*)d_in[2];
    const float* Wq = (const float*)d_in[4];  const float* bq = (const float*)d_in[5];
    const float* Wk = (const float*)d_in[6];  const float* bk = (const float*)d_in[7];
    const float* Wv = (const float*)d_in[8];  const float* bv = (const float*)d_in[9];
    const float* Wo = (const float*)d_in[10]; const float* bo = (const float*)d_in[11];
    float* out = (float*)d_out;

    __nv_bfloat16 *a2p, *w3p, *q2p, *k2p, *vhp, *vlp;
    cudaGetSymbolAddress((void**)&a2p, g_a2);
    cudaGetSymbolAddress((void**)&w3p, g_w3);
    cudaGetSymbolAddress((void**)&q2p, g_q2);
    cudaGetSymbolAddress((void**)&k2p, g_k2);
    cudaGetSymbolAddress((void**)&vhp, g_vh);
    cudaGetSymbolAddress((void**)&vlp, g_vl);

    const int gsm = 6 * 16384;   // 96KB dynamic
    cudaFuncSetAttribute(gemm_qkv, cudaFuncAttributeMaxDynamicSharedMemorySize, gsm);
    cudaFuncSetAttribute(gemm_out, cudaFuncAttributeMaxDynamicSharedMemorySize, gsm);

    // all splits (4 weights + 3 activations) in one launch
    split_all<<<dim3(1024, 7), 256>>>(query, key, value, Wq, Wk, Wv, Wo, a2p, w3p);

    // QKV projections (z-batched) with fused per-head split epilogues
    gemm_qkv<<<dim3(EMB / 128, MTOT / 128, 3), 256, gsm>>>(
        a2p, w3p, bq, bk, bv, q2p, k2p, vhp, vlp);

    // attention -> a2 slot 0 directly
    const int asmem = 98304;
    cudaFuncSetAttribute(attn_hmma, cudaFuncAttributeMaxDynamicSharedMemorySize, asmem);
    attn_hmma<<<dim3(SEQ / 128, NH, BATCH), 256, asmem>>>(q2p, k2p, vhp, vlp, a2p);

    // out projection -> d_out
    gemm_out<<<dim3(EMB / 128, MTOT / 128), 256, gsm>>>(
        a2p, w3p + 3 * (size_t)EMB * KSPLIT, bo, out);
}

// round 10
// speedup vs baseline: 1.1404x; 1.1404x over previous
#include <cuda_runtime.h>
#include <cuda_bf16.h>
#include <cstdint>
#include <cstddef>

#define BATCH 4
#define SEQ   2048
#define EMB   1024
#define NH    16
#define HD    64
#define MTOT  (BATCH * SEQ)        /* 8192 */
#define KSPLIT (3 * EMB)           /* 3072: W-side 3-block */
#define KA2   (2 * EMB)            /* 2048: A-side 2-block [hi|lo] */
#define BK    32
#define NITER (KSPLIT / BK)        /* 96 */
#define LOG2E 1.44269504f
#define NEG_BIG (-1e30f)
#define BHS   ((size_t)BATCH * NH * SEQ)   /* 131072 per-head rows */

// ---------------- scratch (__device__ globals; no allocs) -------------------
__device__ __align__(1024) __nv_bfloat16 g_a2[3][(size_t)MTOT * KA2];   // 3x32MB
__device__ __align__(1024) __nv_bfloat16 g_w3[4][(size_t)EMB * KSPLIT]; // 4x6MB
__device__ __align__(1024) __nv_bfloat16 g_q2[BHS * 128];  // [b,h,s][hi|lo] 32MB
__device__ __align__(1024) __nv_bfloat16 g_k2[BHS * 128];  // 32MB
__device__ __align__(1024) __nv_bfloat16 g_vh[BHS * HD];   // 16MB
__device__ __align__(1024) __nv_bfloat16 g_vl[BHS * HD];   // 16MB

// ---------------- PTX helpers (baseline ISA: sm_80-era ops) -----------------
__device__ __forceinline__ uint32_t smem_u32(const void* p) {
    uint32_t a;
    asm("{ .reg .u64 t; cvta.to.shared.u64 t, %1; cvt.u32.u64 %0, t; }" : "=r"(a) : "l"(p));
    return a;
}
#define CP_ASYNC16(dst, src) \
    asm volatile("cp.async.cg.shared.global [%0], [%1], 16;" :: "r"(dst), "l"(src) : "memory")
#define CP_COMMIT() asm volatile("cp.async.commit_group;" ::: "memory")
#define CP_WAIT1()  asm volatile("cp.async.wait_group 1;" ::: "memory")

__device__ __forceinline__ void ldsm4(uint32_t (&r)[4], uint32_t addr) {
    asm volatile("ldmatrix.sync.aligned.m8n8.x4.shared.b16 {%0,%1,%2,%3}, [%4];"
                 : "=r"(r[0]), "=r"(r[1]), "=r"(r[2]), "=r"(r[3]) : "r"(addr));
}
__device__ __forceinline__ void ldsm4t(uint32_t (&r)[4], uint32_t addr) {
    asm volatile("ldmatrix.sync.aligned.m8n8.x4.trans.shared.b16 {%0,%1,%2,%3}, [%4];"
                 : "=r"(r[0]), "=r"(r[1]), "=r"(r[2]), "=r"(r[3]) : "r"(addr));
}
__device__ __forceinline__ void mma16816(float (&d)[4], const uint32_t (&a)[4],
                                         uint32_t b0, uint32_t b1) {
    asm volatile(
        "mma.sync.aligned.m16n8k16.row.col.f32.bf16.bf16.f32 "
        "{%0,%1,%2,%3}, {%4,%5,%6,%7}, {%8,%9}, {%0,%1,%2,%3};"
        : "+f"(d[0]), "+f"(d[1]), "+f"(d[2]), "+f"(d[3])
        : "r"(a[0]), "r"(a[1]), "r"(a[2]), "r"(a[3]), "r"(b0), "r"(b1));
}
__device__ __forceinline__ uint32_t pk2(__nv_bfloat16 a, __nv_bfloat16 b) {
    __nv_bfloat162 t = __halves2bfloat162(a, b);
    return *reinterpret_cast<uint32_t*>(&t);
}
__device__ __forceinline__ void split1(float v, __nv_bfloat16& h, __nv_bfloat16& l) {
    h = __float2bfloat16(v);
    l = __float2bfloat16(v - __bfloat162float(h));
}

// ---------------------------------------------------------------------------
// split_all (one launch): z<4 -> weights [hi|hi|lo]; z>=4 -> activations [hi|lo]
// ---------------------------------------------------------------------------
__global__ __launch_bounds__(256)
void split_all(const float* __restrict__ q, const float* __restrict__ k,
               const float* __restrict__ v,
               const float* __restrict__ wq, const float* __restrict__ wk,
               const float* __restrict__ wv, const float* __restrict__ wo,
               __nv_bfloat16* __restrict__ a2, __nv_bfloat16* __restrict__ w3)
{
    const int z = blockIdx.y;
    if (z < 4) {
        const float* X = (z == 0) ? wq : (z == 1) ? wk : (z == 2) ? wv : wo;
        __nv_bfloat16* Y = w3 + (size_t)z * EMB * KSPLIT;
        size_t idx = (size_t)blockIdx.x * 256 + threadIdx.x;
        size_t row = idx >> 8;
        int    c   = (int)(idx & 255) << 2;
        float4 x = ((const float4*)X)[idx];
        __nv_bfloat16 h0, h1, h2, h3, l0, l1, l2, l3;
        split1(x.x, h0, l0); split1(x.y, h1, l1);
        split1(x.z, h2, l2); split1(x.w, h3, l3);
        uint2 hv = make_uint2(pk2(h0, h1), pk2(h2, h3));
        uint2 lv = make_uint2(pk2(l0, l1), pk2(l2, l3));
        size_t base = row * (size_t)KSPLIT + c;
        *(uint2*)(Y + base)        = hv;          // hi
        *(uint2*)(Y + base + 1024) = hv;          // hi (2nd block)
        *(uint2*)(Y + base + 2048) = lv;          // lo
    } else {
        const float* X = (z == 4) ? q : (z == 5) ? k : v;
        __nv_bfloat16* Y = a2 + (size_t)(z - 4) * MTOT * KA2;
        #pragma unroll
        for (int t = 0; t < 8; t++) {
            size_t idx = ((size_t)blockIdx.x * 8 + t) * 256 + threadIdx.x;
            size_t row = idx >> 8;
            int    c   = (int)(idx & 255) << 2;
            float4 x = ((const float4*)X)[idx];
            __nv_bfloat16 h0, h1, h2, h3, l0, l1, l2, l3;
            split1(x.x, h0, l0); split1(x.y, h1, l1);
            split1(x.z, h2, l2); split1(x.w, h3, l3);
            size_t base = row * (size_t)KA2 + c;
            *(uint2*)(Y + base)        = make_uint2(pk2(h0, h1), pk2(h2, h3));
            *(uint2*)(Y + base + 1024) = make_uint2(pk2(l0, l1), pk2(l2, l3));
        }
    }
}

// ---------------------------------------------------------------------------
// GEMM core: C = A2[*,2048(LUT->3072)] @ W3[*,3072]^T + bias
// 128 threads / 4 warps, warp tile 64x64 (CUTLASS shape): mma/ldsm = 5.33.
// 6-stage cp.async pipeline in pairs, 1 barrier / 2 k-iters.
// ---------------------------------------------------------------------------
__device__ __forceinline__ int koffA(int it) { return (it < 64 ? it : it - 64) * BK; }

__device__ __forceinline__ void gemm_core(
    const __nv_bfloat16* __restrict__ A, const __nv_bfloat16* __restrict__ W,
    const float* __restrict__ bias, float* __restrict__ Cf,
    __nv_bfloat16* __restrict__ OH, __nv_bfloat16* __restrict__ OL,
    int mode, float scale, int m0, int n0, char* smem_raw)
{
    const uint32_t sbase = smem_u32(smem_raw);

    const int tid  = threadIdx.x;
    const int lane = tid & 31;
    const int wid  = tid >> 5;       // 0..3
    const int wm   = wid >> 1;       // 0..1 : m-offset 64
    const int wn   = wid & 1;        // 0..1 : n-offset 64

    const __nv_bfloat16* Ap = A + (size_t)m0 * KA2;
    const __nv_bfloat16* Wp = W + (size_t)n0 * KSPLIT;

    const int lrow = tid >> 2;       // 0..31
    const int lc   = tid & 3;

    const int arow  = wm * 64 + (lane & 15);
    const int akh   = lane >> 4;
    const int aswz  = (arow >> 1) & 3;
    const int brow  = wn * 64 + (lane & 7) + ((lane & 16) ? 8 : 0);
    const int bkh   = (lane >> 3) & 1;
    const int bswz  = (brow >> 1) & 3;

    float acc[4][8][4];
    #pragma unroll
    for (int i = 0; i < 4; i++)
        #pragma unroll
        for (int j = 0; j < 8; j++)
            #pragma unroll
            for (int k = 0; k < 4; k++) acc[i][j][k] = 0.f;

    // prologue: stages 0..3 as 2 committed pairs (4 A + 4 B chunks per thread/stage)
    #pragma unroll
    for (int s = 0; s < 4; s++) {
        uint32_t sA = sbase + s * 16384;
        uint32_t sB = sA + 8192;
        const __nv_bfloat16* ag = Ap + koffA(s) + lc * 8;
        const __nv_bfloat16* wg = Wp + (size_t)s * BK + lc * 8;
        #pragma unroll
        for (int h = 0; h < 4; h++) {
            int r  = lrow + h * 32;
            int cs = lc ^ ((r >> 1) & 3);
            CP_ASYNC16(sA + r * 64 + cs * 16, ag + (size_t)r * KA2);
            CP_ASYNC16(sB + r * 64 + cs * 16, wg + (size_t)r * KSPLIT);
        }
        if (s & 1) CP_COMMIT();
    }

    int st = 0;
    for (int j = 0; j < NITER / 2; j++) {
        CP_WAIT1();
        __syncthreads();

        #pragma unroll
        for (int half = 0; half < 2; half++) {
            const uint32_t sA = sbase + (st + half) * 16384;
            const uint32_t sB = sA + 8192;
            #pragma unroll
            for (int ks = 0; ks < 2; ks++) {
                uint32_t a[4][4];
                uint32_t b[8][2];
                const int ac = ((ks * 2 + akh) ^ aswz) * 16;
                const int bc = ((ks * 2 + bkh) ^ bswz) * 16;
                #pragma unroll
                for (int mi = 0; mi < 4; mi++)
                    ldsm4(a[mi], sA + (arow + mi * 16) * 64 + ac);
                #pragma unroll
                for (int nj = 0; nj < 4; nj++) {
                    uint32_t t4[4];
                    ldsm4(t4, sB + (brow + nj * 16) * 64 + bc);
                    b[nj * 2][0]     = t4[0]; b[nj * 2][1]     = t4[1];
                    b[nj * 2 + 1][0] = t4[2]; b[nj * 2 + 1][1] = t4[3];
                }
                #pragma unroll
                for (int mi = 0; mi < 4; mi++)
                    #pragma unroll
                    for (int ni = 0; ni < 8; ni++)
                        mma16816(acc[mi][ni], a[mi], b[ni][0], b[ni][1]);
            }
        }

        const int it0 = 2 * j + 4;
        if (it0 < NITER) {
            int pf = st + 4; if (pf >= 6) pf -= 6;
            #pragma unroll
            for (int half = 0; half < 2; half++) {
                const uint32_t dA = sbase + (pf + half) * 16384;
                const uint32_t dB = dA + 8192;
                const __nv_bfloat16* ag = Ap + koffA(it0 + half) + lc * 8;
                const __nv_bfloat16* wg = Wp + (size_t)(it0 + half) * BK + lc * 8;
                #pragma unroll
                for (int h = 0; h < 4; h++) {
                    int r  = lrow + h * 32;
                    int cs = lc ^ ((r >> 1) & 3);
                    CP_ASYNC16(dA + r * 64 + cs * 16, ag + (size_t)r * KA2);
                    CP_ASYNC16(dB + r * 64 + cs * 16, wg + (size_t)r * KSPLIT);
                }
            }
        }
        CP_COMMIT();
        st += 2; if (st >= 6) st -= 6;
    }

    // ---- epilogue ----
    const int trow = lane >> 2;
    const int tcol = (lane & 3) * 2;
    #pragma unroll
    for (int mi = 0; mi < 4; mi++) {
        const int row = m0 + wm * 64 + mi * 16 + trow;
        #pragma unroll
        for (int ni = 0; ni < 8; ni++) {
            const int col = n0 + wn * 64 + ni * 8 + tcol;
            const float b0 = __ldg(bias + col), b1 = __ldg(bias + col + 1);
            float v00 = acc[mi][ni][0] + b0, v01 = acc[mi][ni][1] + b1;
            float v10 = acc[mi][ni][2] + b0, v11 = acc[mi][ni][3] + b1;
            if (mode == 0) {
                *(float2*)(Cf + (size_t)row * EMB + col)       = make_float2(v00, v01);
                *(float2*)(Cf + (size_t)(row + 8) * EMB + col) = make_float2(v10, v11);
            } else {
                v00 *= scale; v01 *= scale; v10 *= scale; v11 *= scale;
                const int hh = col >> 6, d = col & 63;
                const size_t drow = ((size_t)((row >> 11) * NH + hh)) * SEQ + (row & 2047);
                __nv_bfloat16 h0, h1, h2, h3, l0, l1, l2, l3;
                split1(v00, h0, l0); split1(v01, h1, l1);
                split1(v10, h2, l2); split1(v11, h3, l3);
                if (mode == 3) {
                    *(uint32_t*)(OH + drow * HD + d)       = pk2(h0, h1);
                    *(uint32_t*)(OH + (drow + 8) * HD + d) = pk2(h2, h3);
                    *(uint32_t*)(OL + drow * HD + d)       = pk2(l0, l1);
                    *(uint32_t*)(OL + (drow + 8) * HD + d) = pk2(l2, l3);
                } else {
                    __nv_bfloat16* p0 = OH + drow * 128 + d;
                    __nv_bfloat16* p1 = OH + (drow + 8) * 128 + d;
                    *(uint32_t*)(p0)      = pk2(h0, h1);
                    *(uint32_t*)(p0 + 64) = pk2(l0, l1);
                    *(uint32_t*)(p1)      = pk2(h2, h3);
                    *(uint32_t*)(p1 + 64) = pk2(l2, l3);
                }
            }
        }
    }
}

// z-batched QKV projections: z=0 -> q2 (scaled), z=1 -> k2, z=2 -> vh/vl
__global__ __launch_bounds__(128, 2)
void gemm_qkv(const __nv_bfloat16* __restrict__ Abase,
              const __nv_bfloat16* __restrict__ Wbase,
              const float* __restrict__ bq, const float* __restrict__ bk,
              const float* __restrict__ bv,
              __nv_bfloat16* __restrict__ q2, __nv_bfloat16* __restrict__ k2,
              __nv_bfloat16* __restrict__ vh, __nv_bfloat16* __restrict__ vl)
{
    extern __shared__ __align__(1024) char smem_raw[];
    const int z = blockIdx.z;
    const __nv_bfloat16* A = Abase + (size_t)z * MTOT * KA2;
    const __nv_bfloat16* W = Wbase + (size_t)z * EMB * KSPLIT;
    const float* bias = (z == 0) ? bq : (z == 1) ? bk : bv;
    __nv_bfloat16* OH = (z == 0) ? q2 : (z == 1) ? k2 : vh;
    __nv_bfloat16* OL = (z == 2) ? vl : nullptr;
    const float scale = (z == 0) ? 0.125f : 1.0f;
    gemm_core(A, W, bias, nullptr, OH, OL, z + 1, scale,
              blockIdx.y * 128, blockIdx.x * 128, smem_raw);
}

// out projection -> fp32 d_out
__global__ __launch_bounds__(128, 2)
void gemm_out(const __nv_bfloat16* __restrict__ A, const __nv_bfloat16* __restrict__ W,
              const float* __restrict__ bias, float* __restrict__ Cf)
{
    extern __shared__ __align__(1024) char smem_raw[];
    gemm_core(A, W, bias, Cf, nullptr, nullptr, 0, 1.0f,
              blockIdx.y * 128, blockIdx.x * 128, smem_raw);
}

// ---------------------------------------------------------------------------
// HMMA flash attention (causal) — R8 version (stagger reverted).
// Block: 128 queries x 1 head, 8 warps, 64-key tiles, double-buffered.
// ---------------------------------------------------------------------------
__global__ __launch_bounds__(256, 2)
void attn_hmma(const __nv_bfloat16* __restrict__ Q2, const __nv_bfloat16* __restrict__ K2,
               const __nv_bfloat16* __restrict__ VH, const __nv_bfloat16* __restrict__ VL,
               __nv_bfloat16* __restrict__ A2)
{
    extern __shared__ __align__(1024) char smr[];
    const uint32_t sb = smem_u32(smr);
    const uint32_t QS = sb;                 // 4 slabs * 8192B
    const uint32_t KS = sb + 32768;         // 2 stages * 16384
    const uint32_t VS = sb + 65536;         // 2 stages * 16384

    const int tid  = threadIdx.x;
    const int lane = tid & 31;
    const int wid  = tid >> 5;
    const int bx   = gridDim.x - 1 - blockIdx.x;   // LPT: heavy first
    const int head = blockIdx.y;
    const int bz   = blockIdx.z;
    const int qb0  = bx * 128;
    const size_t bh = (size_t)(bz * NH + head);
    const int nkb  = 2 * bx + 2;

    const __nv_bfloat16* Qp = Q2 + (bh * SEQ + qb0) * 128;
    const __nv_bfloat16* Kp = K2 + bh * SEQ * 128;
    const __nv_bfloat16* VHp = VH + bh * SEQ * HD;
    const __nv_bfloat16* VLp = VL + bh * SEQ * HD;

    {
        const int r1 = tid >> 2, lc = tid & 3;
        #pragma unroll
        for (int kc = 0; kc < 4; kc++)
            #pragma unroll
            for (int h = 0; h < 2; h++) {
                int r = r1 + h * 64;
                int cs = lc ^ ((r >> 1) & 3);
                CP_ASYNC16(QS + kc * 8192 + r * 64 + cs * 16,
                           Qp + (size_t)r * 128 + kc * 32 + lc * 8);
            }
        int cs = lc ^ ((r1 >> 1) & 3);
        #pragma unroll
        for (int kc = 0; kc < 4; kc++)
            CP_ASYNC16(KS + kc * 4096 + r1 * 64 + cs * 16,
                       Kp + (size_t)r1 * 128 + kc * 32 + lc * 8);
        const int vr = tid >> 3, vc = tid & 7;
        #pragma unroll
        for (int h = 0; h < 2; h++) {
            int r = vr + h * 32;
            int pc = vc ^ (r & 7);
            CP_ASYNC16(VS + r * 128 + pc * 16, VHp + (size_t)r * HD + vc * 8);
            CP_ASYNC16(VS + 8192 + r * 128 + pc * 16, VLp + (size_t)r * HD + vc * 8);
        }
        CP_COMMIT();
    }

    const int arow = wid * 16 + (lane & 15);
    const int akh  = lane >> 4;
    const int aswz = (arow >> 1) & 3;
    const int brow = (lane & 7) + ((lane & 16) ? 8 : 0);
    const int bkh  = (lane >> 3) & 1;
    const int bswz = (brow >> 1) & 3;
    const int vrow = (lane & 7) + 8 * ((lane >> 3) & 1);
    const int vchb = lane >> 4;
    const int vswz = lane & 7;

    float of[8][4];
    #pragma unroll
    for (int i = 0; i < 8; i++)
        #pragma unroll
        for (int j = 0; j < 4; j++) of[i][j] = 0.f;
    float mq[2] = { NEG_BIG, NEG_BIG };
    float lq[2] = { 0.f, 0.f };

    const int qrow0 = qb0 + wid * 16 + (lane >> 2);

    for (int kb = 0; kb < nkb; kb++) {
        const int st = kb & 1;
        const int kbase = kb * 64;

        if (kb + 1 < nkb) {
            const int nb = (kb + 1) * 64;
            const int s2 = st ^ 1;
            const int r1 = tid >> 2, lc = tid & 3;
            int cs = lc ^ ((r1 >> 1) & 3);
            #pragma unroll
            for (int kc = 0; kc < 4; kc++)
                CP_ASYNC16(KS + s2 * 16384 + kc * 4096 + r1 * 64 + cs * 16,
                           Kp + (size_t)(nb + r1) * 128 + kc * 32 + lc * 8);
            const int vr = tid >> 3, vc = tid & 7;
            #pragma unroll
            for (int h = 0; h < 2; h++) {
                int r = vr + h * 32;
                int pc = vc ^ (r & 7);
                CP_ASYNC16(VS + s2 * 16384 + r * 128 + pc * 16,
                           VHp + (size_t)(nb + r) * HD + vc * 8);
                CP_ASYNC16(VS + s2 * 16384 + 8192 + r * 128 + pc * 16,
                           VLp + (size_t)(nb + r) * HD + vc * 8);
            }
        }
        CP_COMMIT();
        CP_WAIT1();
        __syncthreads();

        float sf[8][4];
        #pragma unroll
        for (int i = 0; i < 8; i++)
            #pragma unroll
            for (int j = 0; j < 4; j++) sf[i][j] = 0.f;

        const uint32_t Kst = KS + st * 16384;
        const int qsel[6] = { 0, 1, 2, 3, 0, 1 };
        const int ksel[6] = { 0, 1, 0, 1, 2, 3 };
        #pragma unroll
        for (int t = 0; t < 6; t++) {
            #pragma unroll
            for (int ks = 0; ks < 2; ks++) {
                uint32_t a[4];
                ldsm4(a, QS + qsel[t] * 8192 + arow * 64 + (((ks * 2 + akh) ^ aswz) * 16));
                const int bc = ((ks * 2 + bkh) ^ bswz) * 16;
                #pragma unroll
                for (int np = 0; np < 4; np++) {
                    uint32_t t4[4];
                    ldsm4(t4, Kst + ksel[t] * 4096 + (np * 16 + brow) * 64 + bc);
                    mma16816(sf[2 * np],     a, t4[0], t4[1]);
                    mma16816(sf[2 * np + 1], a, t4[2], t4[3]);
                }
            }
        }

        if (kb >= nkb - 2) {
            #pragma unroll
            for (int nt = 0; nt < 8; nt++) {
                int col = kbase + nt * 8 + 2 * (lane & 3);
                if (col     > qrow0)     sf[nt][0] = NEG_BIG;
                if (col + 1 > qrow0)     sf[nt][1] = NEG_BIG;
                if (col     > qrow0 + 8) sf[nt][2] = NEG_BIG;
                if (col + 1 > qrow0 + 8) sf[nt][3] = NEG_BIG;
            }
        }

        #pragma unroll
        for (int h = 0; h < 2; h++) {
            float mloc = NEG_BIG;
            #pragma unroll
            for (int nt = 0; nt < 8; nt++)
                mloc = fmaxf(mloc, fmaxf(sf[nt][2 * h], sf[nt][2 * h + 1]));
            mloc = fmaxf(mloc, __shfl_xor_sync(0xffffffffu, mloc, 1));
            mloc = fmaxf(mloc, __shfl_xor_sync(0xffffffffu, mloc, 2));
            float mnew = fmaxf(mq[h], mloc);
            float corr = exp2f((mq[h] - mnew) * LOG2E);
            mq[h] = mnew;
            lq[h] *= corr;
            float ps = 0.f;
            #pragma unroll
            for (int nt = 0; nt < 8; nt++) {
                float p0 = exp2f((sf[nt][2 * h] - mnew) * LOG2E);
                float p1 = exp2f((sf[nt][2 * h + 1] - mnew) * LOG2E);
                sf[nt][2 * h] = p0; sf[nt][2 * h + 1] = p1;
                ps += p0 + p1;
                of[nt][2 * h] *= corr; of[nt][2 * h + 1] *= corr;
            }
            ps += __shfl_xor_sync(0xffffffffu, ps, 1);
            ps += __shfl_xor_sync(0xffffffffu, ps, 2);
            lq[h] += ps;
        }

        const uint32_t Vst = VS + st * 16384;
        #pragma unroll
        for (int kc2 = 0; kc2 < 4; kc2++) {
            const int j0 = 2 * kc2, j1 = j0 + 1;
            uint32_t ph[4], pl[4];
            #pragma unroll
            for (int q = 0; q < 4; q++) {
                const float p0 = (q & 2) ? sf[j1][(q & 1) * 2]     : sf[j0][(q & 1) * 2];
                const float p1 = (q & 2) ? sf[j1][(q & 1) * 2 + 1] : sf[j0][(q & 1) * 2 + 1];
                __nv_bfloat16 h0, h1, l0, l1;
                split1(p0, h0, l0); split1(p1, h1, l1);
                ph[q] = pk2(h0, h1);
                pl[q] = pk2(l0, l1);
            }
            const uint32_t rowoff = (kc2 * 16 + vrow) * 128;
            #pragma unroll
            for (int np = 0; np < 4; np++) {
                const int pc = (2 * np + vchb) ^ vswz;
                uint32_t bh4[4], bl4[4];
                ldsm4t(bh4, Vst + rowoff + pc * 16);
                ldsm4t(bl4, Vst + 8192 + rowoff + pc * 16);
                mma16816(of[2 * np],     ph, bh4[0], bh4[1]);
                mma16816(of[2 * np + 1], ph, bh4[2], bh4[3]);
                mma16816(of[2 * np],     pl, bh4[0], bh4[1]);
                mma16816(of[2 * np + 1], pl, bh4[2], bh4[3]);
                mma16816(of[2 * np],     ph, bl4[0], bl4[1]);
                mma16816(of[2 * np + 1], ph, bl4[2], bl4[3]);
            }
        }
        __syncthreads();
    }

    const float inv0 = 1.f / lq[0];
    const float inv1 = 1.f / lq[1];
    const size_t ar0 = (size_t)bz * SEQ + qb0 + wid * 16 + (lane >> 2);
    const size_t ar1 = ar0 + 8;
    const int colb = head * 64 + 2 * (lane & 3);
    #pragma unroll
    for (int nt = 0; nt < 8; nt++) {
        int col = colb + nt * 8;
        float v0 = of[nt][0] * inv0, v1 = of[nt][1] * inv0;
        float v2 = of[nt][2] * inv1, v3 = of[nt][3] * inv1;
        __nv_bfloat16 h0, h1, h2, h3, l0, l1, l2, l3;
        split1(v0, h0, l0); split1(v1, h1, l1);
        split1(v2, h2, l2); split1(v3, h3, l3);
        __nv_bfloat16* d0 = A2 + ar0 * KA2 + col;
        __nv_bfloat16* d1 = A2 + ar1 * KA2 + col;
        *(uint32_t*)(d0)        = pk2(h0, h1);
        *(uint32_t*)(d0 + 1024) = pk2(l0, l1);
        *(uint32_t*)(d1)        = pk2(h2, h3);
        *(uint32_t*)(d1 + 1024) = pk2(l2, l3);
    }
}

// ---------------------------------------------------------------------------
extern "C" void kernel_launch(void* const* d_in, const int* in_sizes, int n_in,
                              void* d_out, int out_size)
{
    const float* query = (const float*)d_in[0];
    const float* key   = (const float*)d_in[1];
    const float* value = (const float*)d_in[2];
    const float* Wq = (const float*)d_in[4];  const float* bq = (const float*)d_in[5];
    const float* Wk = (const float*)d_in[6];  const float* bk = (const float*)d_in[7];
    const float* Wv = (const float*)d_in[8];  const float* bv = (const float*)d_in[9];
    const float* Wo = (const float*)d_in[10]; const float* bo = (const float*)d_in[11];
    float* out = (float*)d_out;

    __nv_bfloat16 *a2p, *w3p, *q2p, *k2p, *vhp, *vlp;
    cudaGetSymbolAddress((void**)&a2p, g_a2);
    cudaGetSymbolAddress((void**)&w3p, g_w3);
    cudaGetSymbolAddress((void**)&q2p, g_q2);
    cudaGetSymbolAddress((void**)&k2p, g_k2);
    cudaGetSymbolAddress((void**)&vhp, g_vh);
    cudaGetSymbolAddress((void**)&vlp, g_vl);

    const int gsm = 6 * 16384;   // 96KB dynamic
    cudaFuncSetAttribute(gemm_qkv, cudaFuncAttributeMaxDynamicSharedMemorySize, gsm);
    cudaFuncSetAttribute(gemm_out, cudaFuncAttributeMaxDynamicSharedMemorySize, gsm);

    // all splits (4 weights + 3 activations) in one launch
    split_all<<<dim3(1024, 7), 256>>>(query, key, value, Wq, Wk, Wv, Wo, a2p, w3p);

    // QKV projections (z-batched) with fused per-head split epilogues
    gemm_qkv<<<dim3(EMB / 128, MTOT / 128, 3), 128, gsm>>>(
        a2p, w3p, bq, bk, bv, q2p, k2p, vhp, vlp);

    // attention -> a2 slot 0 directly
    const int asmem = 98304;
    cudaFuncSetAttribute(attn_hmma, cudaFuncAttributeMaxDynamicSharedMemorySize, asmem);
    attn_hmma<<<dim3(SEQ / 128, NH, BATCH), 256, asmem>>>(q2p, k2p, vhp, vlp, a2p);

    // out projection -> d_out
    gemm_out<<<dim3(EMB / 128, MTOT / 128), 128, gsm>>>(
        a2p, w3p + 3 * (size_t)EMB * KSPLIT, bo, out);
}

// round 11
// speedup vs baseline: 1.1761x; 1.0313x over previous
#include <cuda_runtime.h>
#include <cuda_bf16.h>
#include <cstdint>
#include <cstddef>

#define BATCH 4
#define SEQ   2048
#define EMB   1024
#define NH    16
#define HD    64
#define MTOT  (BATCH * SEQ)        /* 8192 */
#define KSPLIT (3 * EMB)           /* 3072: W-side 3-block */
#define KA2   (2 * EMB)            /* 2048: A-side 2-block [hi|lo] */
#define BK    32
#define NITER (KSPLIT / BK)        /* 96 */
#define LOG2E 1.44269504f
#define NEG_BIG (-1e30f)
#define BHS   ((size_t)BATCH * NH * SEQ)   /* 131072 per-head rows */

// ---------------- scratch (__device__ globals; no allocs) -------------------
__device__ __align__(1024) __nv_bfloat16 g_a2[3][(size_t)MTOT * KA2];   // 3x32MB
__device__ __align__(1024) __nv_bfloat16 g_w3[4][(size_t)EMB * KSPLIT]; // 4x6MB
__device__ __align__(1024) __nv_bfloat16 g_q2[BHS * 128];  // [b,h,s][hi|lo] 32MB
__device__ __align__(1024) __nv_bfloat16 g_k2[BHS * 128];  // 32MB
__device__ __align__(1024) __nv_bfloat16 g_vh[BHS * HD];   // 16MB
__device__ __align__(1024) __nv_bfloat16 g_vl[BHS * HD];   // 16MB

// ---------------- PTX helpers (baseline ISA: sm_80-era ops) -----------------
__device__ __forceinline__ uint32_t smem_u32(const void* p) {
    uint32_t a;
    asm("{ .reg .u64 t; cvta.to.shared.u64 t, %1; cvt.u32.u64 %0, t; }" : "=r"(a) : "l"(p));
    return a;
}
#define CP_ASYNC16(dst, src) \
    asm volatile("cp.async.cg.shared.global [%0], [%1], 16;" :: "r"(dst), "l"(src) : "memory")
#define CP_COMMIT() asm volatile("cp.async.commit_group;" ::: "memory")
#define CP_WAIT1()  asm volatile("cp.async.wait_group 1;" ::: "memory")

__device__ __forceinline__ void ldsm4(uint32_t (&r)[4], uint32_t addr) {
    asm volatile("ldmatrix.sync.aligned.m8n8.x4.shared.b16 {%0,%1,%2,%3}, [%4];"
                 : "=r"(r[0]), "=r"(r[1]), "=r"(r[2]), "=r"(r[3]) : "r"(addr));
}
__device__ __forceinline__ void ldsm4t(uint32_t (&r)[4], uint32_t addr) {
    asm volatile("ldmatrix.sync.aligned.m8n8.x4.trans.shared.b16 {%0,%1,%2,%3}, [%4];"
                 : "=r"(r[0]), "=r"(r[1]), "=r"(r[2]), "=r"(r[3]) : "r"(addr));
}
__device__ __forceinline__ void mma16816(float (&d)[4], const uint32_t (&a)[4],
                                         uint32_t b0, uint32_t b1) {
    asm volatile(
        "mma.sync.aligned.m16n8k16.row.col.f32.bf16.bf16.f32 "
        "{%0,%1,%2,%3}, {%4,%5,%6,%7}, {%8,%9}, {%0,%1,%2,%3};"
        : "+f"(d[0]), "+f"(d[1]), "+f"(d[2]), "+f"(d[3])
        : "r"(a[0]), "r"(a[1]), "r"(a[2]), "r"(a[3]), "r"(b0), "r"(b1));
}
__device__ __forceinline__ uint32_t pk2(__nv_bfloat16 a, __nv_bfloat16 b) {
    __nv_bfloat162 t = __halves2bfloat162(a, b);
    return *reinterpret_cast<uint32_t*>(&t);
}
__device__ __forceinline__ void split1(float v, __nv_bfloat16& h, __nv_bfloat16& l) {
    h = __float2bfloat16(v);
    l = __float2bfloat16(v - __bfloat162float(h));
}

// ---------------------------------------------------------------------------
// split_all (one launch): z<4 -> weights [hi|hi|lo]; z>=4 -> activations [hi|lo]
// ---------------------------------------------------------------------------
__global__ __launch_bounds__(256)
void split_all(const float* __restrict__ q, const float* __restrict__ k,
               const float* __restrict__ v,
               const float* __restrict__ wq, const float* __restrict__ wk,
               const float* __restrict__ wv, const float* __restrict__ wo,
               __nv_bfloat16* __restrict__ a2, __nv_bfloat16* __restrict__ w3)
{
    const int z = blockIdx.y;
    if (z < 4) {
        const float* X = (z == 0) ? wq : (z == 1) ? wk : (z == 2) ? wv : wo;
        __nv_bfloat16* Y = w3 + (size_t)z * EMB * KSPLIT;
        size_t idx = (size_t)blockIdx.x * 256 + threadIdx.x;
        size_t row = idx >> 8;
        int    c   = (int)(idx & 255) << 2;
        float4 x = ((const float4*)X)[idx];
        __nv_bfloat16 h0, h1, h2, h3, l0, l1, l2, l3;
        split1(x.x, h0, l0); split1(x.y, h1, l1);
        split1(x.z, h2, l2); split1(x.w, h3, l3);
        uint2 hv = make_uint2(pk2(h0, h1), pk2(h2, h3));
        uint2 lv = make_uint2(pk2(l0, l1), pk2(l2, l3));
        size_t base = row * (size_t)KSPLIT + c;
        *(uint2*)(Y + base)        = hv;          // hi
        *(uint2*)(Y + base + 1024) = hv;          // hi (2nd block)
        *(uint2*)(Y + base + 2048) = lv;          // lo
    } else {
        const float* X = (z == 4) ? q : (z == 5) ? k : v;
        __nv_bfloat16* Y = a2 + (size_t)(z - 4) * MTOT * KA2;
        #pragma unroll
        for (int t = 0; t < 8; t++) {
            size_t idx = ((size_t)blockIdx.x * 8 + t) * 256 + threadIdx.x;
            size_t row = idx >> 8;
            int    c   = (int)(idx & 255) << 2;
            float4 x = ((const float4*)X)[idx];
            __nv_bfloat16 h0, h1, h2, h3, l0, l1, l2, l3;
            split1(x.x, h0, l0); split1(x.y, h1, l1);
            split1(x.z, h2, l2); split1(x.w, h3, l3);
            size_t base = row * (size_t)KA2 + c;
            *(uint2*)(Y + base)        = make_uint2(pk2(h0, h1), pk2(h2, h3));
            *(uint2*)(Y + base + 1024) = make_uint2(pk2(l0, l1), pk2(l2, l3));
        }
    }
}

// ---------------------------------------------------------------------------
// GEMM core (R8 config): C = A2[*,2048(LUT->3072)] @ W3[*,3072]^T + bias
// 256 threads / 8 warps, warp tile 64x32.
// 6-stage cp.async pipeline in pairs, 1 barrier / 2 k-iters.
// ---------------------------------------------------------------------------
__device__ __forceinline__ int koffA(int it) { return (it < 64 ? it : it - 64) * BK; }

__device__ __forceinline__ void gemm_core(
    const __nv_bfloat16* __restrict__ A, const __nv_bfloat16* __restrict__ W,
    const float* __restrict__ bias, float* __restrict__ Cf,
    __nv_bfloat16* __restrict__ OH, __nv_bfloat16* __restrict__ OL,
    int mode, float scale, int m0, int n0, char* smem_raw)
{
    const uint32_t sbase = smem_u32(smem_raw);

    const int tid  = threadIdx.x;
    const int lane = tid & 31;
    const int wid  = tid >> 5;
    const int wm   = wid >> 2;
    const int wn   = wid & 3;

    const __nv_bfloat16* Ap = A + (size_t)m0 * KA2;
    const __nv_bfloat16* Wp = W + (size_t)n0 * KSPLIT;

    const int lrow = tid >> 2;
    const int lc   = tid & 3;

    const int arow  = wm * 64 + (lane & 15);
    const int akh   = lane >> 4;
    const int aswz  = (arow >> 1) & 3;
    const int brow  = wn * 32 + (lane & 7) + ((lane & 16) ? 8 : 0);
    const int bkh   = (lane >> 3) & 1;
    const int bswz  = (brow >> 1) & 3;

    float acc[4][4][4];
    #pragma unroll
    for (int i = 0; i < 4; i++)
        #pragma unroll
        for (int j = 0; j < 4; j++)
            #pragma unroll
            for (int k = 0; k < 4; k++) acc[i][j][k] = 0.f;

    // prologue: stages 0..3 as 2 committed pairs
    #pragma unroll
    for (int s = 0; s < 4; s++) {
        uint32_t sA = sbase + s * 16384;
        uint32_t sB = sA + 8192;
        const __nv_bfloat16* ag = Ap + koffA(s) + lc * 8;
        const __nv_bfloat16* wg = Wp + (size_t)s * BK + lc * 8;
        #pragma unroll
        for (int h = 0; h < 2; h++) {
            int r  = lrow + h * 64;
            int cs = lc ^ ((r >> 1) & 3);
            CP_ASYNC16(sA + r * 64 + cs * 16, ag + (size_t)r * KA2);
            CP_ASYNC16(sB + r * 64 + cs * 16, wg + (size_t)r * KSPLIT);
        }
        if (s & 1) CP_COMMIT();
    }

    int st = 0;
    for (int j = 0; j < NITER / 2; j++) {
        CP_WAIT1();
        __syncthreads();

        #pragma unroll
        for (int half = 0; half < 2; half++) {
            const uint32_t sA = sbase + (st + half) * 16384;
            const uint32_t sB = sA + 8192;
            #pragma unroll
            for (int ks = 0; ks < 2; ks++) {
                uint32_t a[4][4];
                uint32_t b[4][2];
                const int ac = ((ks * 2 + akh) ^ aswz) * 16;
                const int bc = ((ks * 2 + bkh) ^ bswz) * 16;
                #pragma unroll
                for (int mi = 0; mi < 4; mi++)
                    ldsm4(a[mi], sA + (arow + mi * 16) * 64 + ac);
                #pragma unroll
                for (int nj = 0; nj < 2; nj++) {
                    uint32_t t4[4];
                    ldsm4(t4, sB + (brow + nj * 16) * 64 + bc);
                    b[nj * 2][0]     = t4[0]; b[nj * 2][1]     = t4[1];
                    b[nj * 2 + 1][0] = t4[2]; b[nj * 2 + 1][1] = t4[3];
                }
                #pragma unroll
                for (int mi = 0; mi < 4; mi++)
                    #pragma unroll
                    for (int ni = 0; ni < 4; ni++)
                        mma16816(acc[mi][ni], a[mi], b[ni][0], b[ni][1]);
            }
        }

        const int it0 = 2 * j + 4;
        if (it0 < NITER) {
            int pf = st + 4; if (pf >= 6) pf -= 6;
            #pragma unroll
            for (int half = 0; half < 2; half++) {
                const uint32_t dA = sbase + (pf + half) * 16384;
                const uint32_t dB = dA + 8192;
                const __nv_bfloat16* ag = Ap + koffA(it0 + half) + lc * 8;
                const __nv_bfloat16* wg = Wp + (size_t)(it0 + half) * BK + lc * 8;
                #pragma unroll
                for (int h = 0; h < 2; h++) {
                    int r  = lrow + h * 64;
                    int cs = lc ^ ((r >> 1) & 3);
                    CP_ASYNC16(dA + r * 64 + cs * 16, ag + (size_t)r * KA2);
                    CP_ASYNC16(dB + r * 64 + cs * 16, wg + (size_t)r * KSPLIT);
                }
            }
        }
        CP_COMMIT();
        st += 2; if (st >= 6) st -= 6;
    }

    // ---- epilogue ----
    const int trow = lane >> 2;
    const int tcol = (lane & 3) * 2;
    #pragma unroll
    for (int mi = 0; mi < 4; mi++) {
        const int row = m0 + wm * 64 + mi * 16 + trow;
        #pragma unroll
        for (int ni = 0; ni < 4; ni++) {
            const int col = n0 + wn * 32 + ni * 8 + tcol;
            const float b0 = __ldg(bias + col), b1 = __ldg(bias + col + 1);
            float v00 = acc[mi][ni][0] + b0, v01 = acc[mi][ni][1] + b1;
            float v10 = acc[mi][ni][2] + b0, v11 = acc[mi][ni][3] + b1;
            if (mode == 0) {
                *(float2*)(Cf + (size_t)row * EMB + col)       = make_float2(v00, v01);
                *(float2*)(Cf + (size_t)(row + 8) * EMB + col) = make_float2(v10, v11);
            } else {
                v00 *= scale; v01 *= scale; v10 *= scale; v11 *= scale;
                const int hh = col >> 6, d = col & 63;
                const size_t drow = ((size_t)((row >> 11) * NH + hh)) * SEQ + (row & 2047);
                __nv_bfloat16 h0, h1, h2, h3, l0, l1, l2, l3;
                split1(v00, h0, l0); split1(v01, h1, l1);
                split1(v10, h2, l2); split1(v11, h3, l3);
                if (mode == 3) {
                    *(uint32_t*)(OH + drow * HD + d)       = pk2(h0, h1);
                    *(uint32_t*)(OH + (drow + 8) * HD + d) = pk2(h2, h3);
                    *(uint32_t*)(OL + drow * HD + d)       = pk2(l0, l1);
                    *(uint32_t*)(OL + (drow + 8) * HD + d) = pk2(l2, l3);
                } else {
                    __nv_bfloat16* p0 = OH + drow * 128 + d;
                    __nv_bfloat16* p1 = OH + (drow + 8) * 128 + d;
                    *(uint32_t*)(p0)      = pk2(h0, h1);
                    *(uint32_t*)(p0 + 64) = pk2(l0, l1);
                    *(uint32_t*)(p1)      = pk2(h2, h3);
                    *(uint32_t*)(p1 + 64) = pk2(l2, l3);
                }
            }
        }
    }
}

// z-batched QKV projections: z=0 -> q2 (scaled), z=1 -> k2, z=2 -> vh/vl
__global__ __launch_bounds__(256, 2)
void gemm_qkv(const __nv_bfloat16* __restrict__ Abase,
              const __nv_bfloat16* __restrict__ Wbase,
              const float* __restrict__ bq, const float* __restrict__ bk,
              const float* __restrict__ bv,
              __nv_bfloat16* __restrict__ q2, __nv_bfloat16* __restrict__ k2,
              __nv_bfloat16* __restrict__ vh, __nv_bfloat16* __restrict__ vl)
{
    extern __shared__ __align__(1024) char smem_raw[];
    const int z = blockIdx.z;
    const __nv_bfloat16* A = Abase + (size_t)z * MTOT * KA2;
    const __nv_bfloat16* W = Wbase + (size_t)z * EMB * KSPLIT;
    const float* bias = (z == 0) ? bq : (z == 1) ? bk : bv;
    __nv_bfloat16* OH = (z == 0) ? q2 : (z == 1) ? k2 : vh;
    __nv_bfloat16* OL = (z == 2) ? vl : nullptr;
    const float scale = (z == 0) ? 0.125f : 1.0f;
    gemm_core(A, W, bias, nullptr, OH, OL, z + 1, scale,
              blockIdx.y * 128, blockIdx.x * 128, smem_raw);
}

// out projection -> fp32 d_out
__global__ __launch_bounds__(256, 2)
void gemm_out(const __nv_bfloat16* __restrict__ A, const __nv_bfloat16* __restrict__ W,
              const float* __restrict__ bias, float* __restrict__ Cf)
{
    extern __shared__ __align__(1024) char smem_raw[];
    gemm_core(A, W, bias, Cf, nullptr, nullptr, 0, 1.0f,
              blockIdx.y * 128, blockIdx.x * 128, smem_raw);
}

// ---------------------------------------------------------------------------
// HMMA flash attention (causal), bf16 3-term via 2-block [hi|lo] operands.
// QK loop grouped by K-slab: K fragments loaded once per (slab,ks), reused
// across the q-slab terms sharing them (48 -> 32 K-ldsm per tile).
// ---------------------------------------------------------------------------
__global__ __launch_bounds__(256, 2)
void attn_hmma(const __nv_bfloat16* __restrict__ Q2, const __nv_bfloat16* __restrict__ K2,
               const __nv_bfloat16* __restrict__ VH, const __nv_bfloat16* __restrict__ VL,
               __nv_bfloat16* __restrict__ A2)
{
    extern __shared__ __align__(1024) char smr[];
    const uint32_t sb = smem_u32(smr);
    const uint32_t QS = sb;                 // 4 slabs * 8192B
    const uint32_t KS = sb + 32768;         // 2 stages * 16384
    const uint32_t VS = sb + 65536;         // 2 stages * 16384

    const int tid  = threadIdx.x;
    const int lane = tid & 31;
    const int wid  = tid >> 5;
    const int bx   = gridDim.x - 1 - blockIdx.x;   // LPT: heavy first
    const int head = blockIdx.y;
    const int bz   = blockIdx.z;
    const int qb0  = bx * 128;
    const size_t bh = (size_t)(bz * NH + head);
    const int nkb  = 2 * bx + 2;

    const __nv_bfloat16* Qp = Q2 + (bh * SEQ + qb0) * 128;
    const __nv_bfloat16* Kp = K2 + bh * SEQ * 128;
    const __nv_bfloat16* VHp = VH + bh * SEQ * HD;
    const __nv_bfloat16* VLp = VL + bh * SEQ * HD;

    {
        const int r1 = tid >> 2, lc = tid & 3;
        #pragma unroll
        for (int kc = 0; kc < 4; kc++)
            #pragma unroll
            for (int h = 0; h < 2; h++) {
                int r = r1 + h * 64;
                int cs = lc ^ ((r >> 1) & 3);
                CP_ASYNC16(QS + kc * 8192 + r * 64 + cs * 16,
                           Qp + (size_t)r * 128 + kc * 32 + lc * 8);
            }
        int cs = lc ^ ((r1 >> 1) & 3);
        #pragma unroll
        for (int kc = 0; kc < 4; kc++)
            CP_ASYNC16(KS + kc * 4096 + r1 * 64 + cs * 16,
                       Kp + (size_t)r1 * 128 + kc * 32 + lc * 8);
        const int vr = tid >> 3, vc = tid & 7;
        #pragma unroll
        for (int h = 0; h < 2; h++) {
            int r = vr + h * 32;
            int pc = vc ^ (r & 7);
            CP_ASYNC16(VS + r * 128 + pc * 16, VHp + (size_t)r * HD + vc * 8);
            CP_ASYNC16(VS + 8192 + r * 128 + pc * 16, VLp + (size_t)r * HD + vc * 8);
        }
        CP_COMMIT();
    }

    const int arow = wid * 16 + (lane & 15);
    const int akh  = lane >> 4;
    const int aswz = (arow >> 1) & 3;
    const int brow = (lane & 7) + ((lane & 16) ? 8 : 0);
    const int bkh  = (lane >> 3) & 1;
    const int bswz = (brow >> 1) & 3;
    const int vrow = (lane & 7) + 8 * ((lane >> 3) & 1);
    const int vchb = lane >> 4;
    const int vswz = lane & 7;

    float of[8][4];
    #pragma unroll
    for (int i = 0; i < 8; i++)
        #pragma unroll
        for (int j = 0; j < 4; j++) of[i][j] = 0.f;
    float mq[2] = { NEG_BIG, NEG_BIG };
    float lq[2] = { 0.f, 0.f };

    const int qrow0 = qb0 + wid * 16 + (lane >> 2);

    for (int kb = 0; kb < nkb; kb++) {
        const int st = kb & 1;
        const int kbase = kb * 64;

        if (kb + 1 < nkb) {
            const int nb = (kb + 1) * 64;
            const int s2 = st ^ 1;
            const int r1 = tid >> 2, lc = tid & 3;
            int cs = lc ^ ((r1 >> 1) & 3);
            #pragma unroll
            for (int kc = 0; kc < 4; kc++)
                CP_ASYNC16(KS + s2 * 16384 + kc * 4096 + r1 * 64 + cs * 16,
                           Kp + (size_t)(nb + r1) * 128 + kc * 32 + lc * 8);
            const int vr = tid >> 3, vc = tid & 7;
            #pragma unroll
            for (int h = 0; h < 2; h++) {
                int r = vr + h * 32;
                int pc = vc ^ (r & 7);
                CP_ASYNC16(VS + s2 * 16384 + r * 128 + pc * 16,
                           VHp + (size_t)(nb + r) * HD + vc * 8);
                CP_ASYNC16(VS + s2 * 16384 + 8192 + r * 128 + pc * 16,
                           VLp + (size_t)(nb + r) * HD + vc * 8);
            }
        }
        CP_COMMIT();
        CP_WAIT1();
        __syncthreads();

        // ---- S = 3-term QK^T, grouped by K-slab for fragment reuse ----
        float sf[8][4];
        #pragma unroll
        for (int i = 0; i < 8; i++)
            #pragma unroll
            for (int j = 0; j < 4; j++) sf[i][j] = 0.f;

        const uint32_t Kst = KS + st * 16384;
        // groups: k-slab g; g<2 serves q-slabs {g, g+2}, g>=2 serves {g-2}
        #pragma unroll
        for (int g = 0; g < 4; g++) {
            const int nq = (g < 2) ? 2 : 1;
            #pragma unroll
            for (int ks = 0; ks < 2; ks++) {
                const int bc = ((ks * 2 + bkh) ^ bswz) * 16;
                uint32_t kf[4][4];
                #pragma unroll
                for (int np = 0; np < 4; np++)
                    ldsm4(kf[np], Kst + g * 4096 + (np * 16 + brow) * 64 + bc);
                #pragma unroll
                for (int qi = 0; qi < 2; qi++) {
                    if (qi < nq) {
                        const int qs = (g < 2) ? (g + qi * 2) : (g - 2);
                        uint32_t a[4];
                        ldsm4(a, QS + qs * 8192 + arow * 64 +
                                 (((ks * 2 + akh) ^ aswz) * 16));
                        #pragma unroll
                        for (int np = 0; np < 4; np++) {
                            mma16816(sf[2 * np],     a, kf[np][0], kf[np][1]);
                            mma16816(sf[2 * np + 1], a, kf[np][2], kf[np][3]);
                        }
                    }
                }
            }
        }

        if (kb >= nkb - 2) {
            #pragma unroll
            for (int nt = 0; nt < 8; nt++) {
                int col = kbase + nt * 8 + 2 * (lane & 3);
                if (col     > qrow0)     sf[nt][0] = NEG_BIG;
                if (col + 1 > qrow0)     sf[nt][1] = NEG_BIG;
                if (col     > qrow0 + 8) sf[nt][2] = NEG_BIG;
                if (col + 1 > qrow0 + 8) sf[nt][3] = NEG_BIG;
            }
        }

        #pragma unroll
        for (int h = 0; h < 2; h++) {
            float mloc = NEG_BIG;
            #pragma unroll
            for (int nt = 0; nt < 8; nt++)
                mloc = fmaxf(mloc, fmaxf(sf[nt][2 * h], sf[nt][2 * h + 1]));
            mloc = fmaxf(mloc, __shfl_xor_sync(0xffffffffu, mloc, 1));
            mloc = fmaxf(mloc, __shfl_xor_sync(0xffffffffu, mloc, 2));
            float mnew = fmaxf(mq[h], mloc);
            float corr = exp2f((mq[h] - mnew) * LOG2E);
            mq[h] = mnew;
            lq[h] *= corr;
            float ps = 0.f;
            #pragma unroll
            for (int nt = 0; nt < 8; nt++) {
                float p0 = exp2f((sf[nt][2 * h] - mnew) * LOG2E);
                float p1 = exp2f((sf[nt][2 * h + 1] - mnew) * LOG2E);
                sf[nt][2 * h] = p0; sf[nt][2 * h + 1] = p1;
                ps += p0 + p1;
                of[nt][2 * h] *= corr; of[nt][2 * h + 1] *= corr;
            }
            ps += __shfl_xor_sync(0xffffffffu, ps, 1);
            ps += __shfl_xor_sync(0xffffffffu, ps, 2);
            lq[h] += ps;
        }

        const uint32_t Vst = VS + st * 16384;
        #pragma unroll
        for (int kc2 = 0; kc2 < 4; kc2++) {
            const int j0 = 2 * kc2, j1 = j0 + 1;
            uint32_t ph[4], pl[4];
            #pragma unroll
            for (int q = 0; q < 4; q++) {
                const float p0 = (q & 2) ? sf[j1][(q & 1) * 2]     : sf[j0][(q & 1) * 2];
                const float p1 = (q & 2) ? sf[j1][(q & 1) * 2 + 1] : sf[j0][(q & 1) * 2 + 1];
                __nv_bfloat16 h0, h1, l0, l1;
                split1(p0, h0, l0); split1(p1, h1, l1);
                ph[q] = pk2(h0, h1);
                pl[q] = pk2(l0, l1);
            }
            const uint32_t rowoff = (kc2 * 16 + vrow) * 128;
            #pragma unroll
            for (int np = 0; np < 4; np++) {
                const int pc = (2 * np + vchb) ^ vswz;
                uint32_t bh4[4], bl4[4];
                ldsm4t(bh4, Vst + rowoff + pc * 16);
                ldsm4t(bl4, Vst + 8192 + rowoff + pc * 16);
                mma16816(of[2 * np],     ph, bh4[0], bh4[1]);
                mma16816(of[2 * np + 1], ph, bh4[2], bh4[3]);
                mma16816(of[2 * np],     pl, bh4[0], bh4[1]);
                mma16816(of[2 * np + 1], pl, bh4[2], bh4[3]);
                mma16816(of[2 * np],     ph, bl4[0], bl4[1]);
                mma16816(of[2 * np + 1], ph, bl4[2], bl4[3]);
            }
        }
        __syncthreads();
    }

    const float inv0 = 1.f / lq[0];
    const float inv1 = 1.f / lq[1];
    const size_t ar0 = (size_t)bz * SEQ + qb0 + wid * 16 + (lane >> 2);
    const size_t ar1 = ar0 + 8;
    const int colb = head * 64 + 2 * (lane & 3);
    #pragma unroll
    for (int nt = 0; nt < 8; nt++) {
        int col = colb + nt * 8;
        float v0 = of[nt][0] * inv0, v1 = of[nt][1] * inv0;
        float v2 = of[nt][2] * inv1, v3 = of[nt][3] * inv1;
        __nv_bfloat16 h0, h1, h2, h3, l0, l1, l2, l3;
        split1(v0, h0, l0); split1(v1, h1, l1);
        split1(v2, h2, l2); split1(v3, h3, l3);
        __nv_bfloat16* d0 = A2 + ar0 * KA2 + col;
        __nv_bfloat16* d1 = A2 + ar1 * KA2 + col;
        *(uint32_t*)(d0)        = pk2(h0, h1);
        *(uint32_t*)(d0 + 1024) = pk2(l0, l1);
        *(uint32_t*)(d1)        = pk2(h2, h3);
        *(uint32_t*)(d1 + 1024) = pk2(l2, l3);
    }
}

// ---------------------------------------------------------------------------
extern "C" void kernel_launch(void* const* d_in, const int* in_sizes, int n_in,
                              void* d_out, int out_size)
{
    const float* query = (const float*)d_in[0];
    const float* key   = (const float*)d_in[1];
    const float* value = (const float*)d_in[2];
    const float* Wq = (const float*)d_in[4];  const float* bq = (const float*)d_in[5];
    const float* Wk = (const float*)d_in[6];  const float* bk = (const float*)d_in[7];
    const float* Wv = (const float*)d_in[8];  const float* bv = (const float*)d_in[9];
    const float* Wo = (const float*)d_in[10]; const float* bo = (const float*)d_in[11];
    float* out = (float*)d_out;

    __nv_bfloat16 *a2p, *w3p, *q2p, *k2p, *vhp, *vlp;
    cudaGetSymbolAddress((void**)&a2p, g_a2);
    cudaGetSymbolAddress((void**)&w3p, g_w3);
    cudaGetSymbolAddress((void**)&q2p, g_q2);
    cudaGetSymbolAddress((void**)&k2p, g_k2);
    cudaGetSymbolAddress((void**)&vhp, g_vh);
    cudaGetSymbolAddress((void**)&vlp, g_vl);

    const int gsm = 6 * 16384;   // 96KB dynamic
    cudaFuncSetAttribute(gemm_qkv, cudaFuncAttributeMaxDynamicSharedMemorySize, gsm);
    cudaFuncSetAttribute(gemm_out, cudaFuncAttributeMaxDynamicSharedMemorySize, gsm);

    // all splits (4 weights + 3 activations) in one launch
    split_all<<<dim3(1024, 7), 256>>>(query, key, value, Wq, Wk, Wv, Wo, a2p, w3p);

    // QKV projections (z-batched) with fused per-head split epilogues
    gemm_qkv<<<dim3(EMB / 128, MTOT / 128, 3), 256, gsm>>>(
        a2p, w3p, bq, bk, bv, q2p, k2p, vhp, vlp);

    // attention -> a2 slot 0 directly
    const int asmem = 98304;
    cudaFuncSetAttribute(attn_hmma, cudaFuncAttributeMaxDynamicSharedMemorySize, asmem);
    attn_hmma<<<dim3(SEQ / 128, NH, BATCH), 256, asmem>>>(q2p, k2p, vhp, vlp, a2p);

    // out projection -> d_out
    gemm_out<<<dim3(EMB / 128, MTOT / 128), 256, gsm>>>(
        a2p, w3p + 3 * (size_t)EMB * KSPLIT, bo, out);
}

// round 12
// speedup vs baseline: 1.3318x; 1.1324x over previous
#include <cuda_runtime.h>
#include <cuda_bf16.h>
#include <cuda_fp16.h>
#include <cstdint>
#include <cstddef>

#define BATCH 4
#define SEQ   2048
#define EMB   1024
#define NH    16
#define HD    64
#define MTOT  (BATCH * SEQ)        /* 8192 */
#define KSPLIT (3 * EMB)           /* 3072: W-side 3-block (bf16 GEMMs) */
#define KA2   (2 * EMB)            /* 2048: A-side 2-block [hi|lo] */
#define BK    32
#define NITER (KSPLIT / BK)        /* 96 */
#define LOG2E 1.44269504f
#define NEG_BIG (-1e30f)
#define BHS   ((size_t)BATCH * NH * SEQ)   /* 131072 per-head rows */

// ---------------- scratch (__device__ globals; no allocs) -------------------
__device__ __align__(1024) __nv_bfloat16 g_a2[3][(size_t)MTOT * KA2];   // 3x32MB
__device__ __align__(1024) __nv_bfloat16 g_w3[4][(size_t)EMB * KSPLIT]; // 4x6MB
__device__ __align__(1024) __half g_q2[BHS * 128];  // [b,h,s][qh|ql] fp16 32MB
__device__ __align__(1024) __half g_k2[BHS * 64];   // [b,h,s][kh] fp16 16MB
__device__ __align__(1024) __half g_vh[BHS * 64];   // [b,h,s][vh] fp16 16MB

// ---------------- PTX helpers (baseline ISA: sm_80-era ops) -----------------
__device__ __forceinline__ uint32_t smem_u32(const void* p) {
    uint32_t a;
    asm("{ .reg .u64 t; cvta.to.shared.u64 t, %1; cvt.u32.u64 %0, t; }" : "=r"(a) : "l"(p));
    return a;
}
#define CP_ASYNC16(dst, src) \
    asm volatile("cp.async.cg.shared.global [%0], [%1], 16;" :: "r"(dst), "l"(src) : "memory")
#define CP_COMMIT() asm volatile("cp.async.commit_group;" ::: "memory")
#define CP_WAIT1()  asm volatile("cp.async.wait_group 1;" ::: "memory")

__device__ __forceinline__ void ldsm4(uint32_t (&r)[4], uint32_t addr) {
    asm volatile("ldmatrix.sync.aligned.m8n8.x4.shared.b16 {%0,%1,%2,%3}, [%4];"
                 : "=r"(r[0]), "=r"(r[1]), "=r"(r[2]), "=r"(r[3]) : "r"(addr));
}
__device__ __forceinline__ void ldsm4t(uint32_t (&r)[4], uint32_t addr) {
    asm volatile("ldmatrix.sync.aligned.m8n8.x4.trans.shared.b16 {%0,%1,%2,%3}, [%4];"
                 : "=r"(r[0]), "=r"(r[1]), "=r"(r[2]), "=r"(r[3]) : "r"(addr));
}
__device__ __forceinline__ void mma16816(float (&d)[4], const uint32_t (&a)[4],
                                         uint32_t b0, uint32_t b1) {
    asm volatile(
        "mma.sync.aligned.m16n8k16.row.col.f32.bf16.bf16.f32 "
        "{%0,%1,%2,%3}, {%4,%5,%6,%7}, {%8,%9}, {%0,%1,%2,%3};"
        : "+f"(d[0]), "+f"(d[1]), "+f"(d[2]), "+f"(d[3])
        : "r"(a[0]), "r"(a[1]), "r"(a[2]), "r"(a[3]), "r"(b0), "r"(b1));
}
__device__ __forceinline__ void mma16816h(float (&d)[4], const uint32_t (&a)[4],
                                          uint32_t b0, uint32_t b1) {
    asm volatile(
        "mma.sync.aligned.m16n8k16.row.col.f32.f16.f16.f32 "
        "{%0,%1,%2,%3}, {%4,%5,%6,%7}, {%8,%9}, {%0,%1,%2,%3};"
        : "+f"(d[0]), "+f"(d[1]), "+f"(d[2]), "+f"(d[3])
        : "r"(a[0]), "r"(a[1]), "r"(a[2]), "r"(a[3]), "r"(b0), "r"(b1));
}
__device__ __forceinline__ uint32_t pk2(__nv_bfloat16 a, __nv_bfloat16 b) {
    __nv_bfloat162 t = __halves2bfloat162(a, b);
    return *reinterpret_cast<uint32_t*>(&t);
}
__device__ __forceinline__ void split1(float v, __nv_bfloat16& h, __nv_bfloat16& l) {
    h = __float2bfloat16(v);
    l = __float2bfloat16(v - __bfloat162float(h));
}
__device__ __forceinline__ uint32_t pk2h(__half a, __half b) {
    __half2 t = __halves2half2(a, b);
    return *reinterpret_cast<uint32_t*>(&t);
}
__device__ __forceinline__ void split1h(float v, __half& h, __half& l) {
    h = __float2half_rn(v);
    l = __float2half_rn(v - __half2float(h));
}

// ---------------------------------------------------------------------------
// split_all (one launch): z<4 -> weights [hi|hi|lo]; z>=4 -> activations [hi|lo]
// ---------------------------------------------------------------------------
__global__ __launch_bounds__(256)
void split_all(const float* __restrict__ q, const float* __restrict__ k,
               const float* __restrict__ v,
               const float* __restrict__ wq, const float* __restrict__ wk,
               const float* __restrict__ wv, const float* __restrict__ wo,
               __nv_bfloat16* __restrict__ a2, __nv_bfloat16* __restrict__ w3)
{
    const int z = blockIdx.y;
    if (z < 4) {
        const float* X = (z == 0) ? wq : (z == 1) ? wk : (z == 2) ? wv : wo;
        __nv_bfloat16* Y = w3 + (size_t)z * EMB * KSPLIT;
        size_t idx = (size_t)blockIdx.x * 256 + threadIdx.x;
        size_t row = idx >> 8;
        int    c   = (int)(idx & 255) << 2;
        float4 x = ((const float4*)X)[idx];
        __nv_bfloat16 h0, h1, h2, h3, l0, l1, l2, l3;
        split1(x.x, h0, l0); split1(x.y, h1, l1);
        split1(x.z, h2, l2); split1(x.w, h3, l3);
        uint2 hv = make_uint2(pk2(h0, h1), pk2(h2, h3));
        uint2 lv = make_uint2(pk2(l0, l1), pk2(l2, l3));
        size_t base = row * (size_t)KSPLIT + c;
        *(uint2*)(Y + base)        = hv;          // hi
        *(uint2*)(Y + base + 1024) = hv;          // hi (2nd block)
        *(uint2*)(Y + base + 2048) = lv;          // lo
    } else {
        const float* X = (z == 4) ? q : (z == 5) ? k : v;
        __nv_bfloat16* Y = a2 + (size_t)(z - 4) * MTOT * KA2;
        #pragma unroll
        for (int t = 0; t < 8; t++) {
            size_t idx = ((size_t)blockIdx.x * 8 + t) * 256 + threadIdx.x;
            size_t row = idx >> 8;
            int    c   = (int)(idx & 255) << 2;
            float4 x = ((const float4*)X)[idx];
            __nv_bfloat16 h0, h1, h2, h3, l0, l1, l2, l3;
            split1(x.x, h0, l0); split1(x.y, h1, l1);
            split1(x.z, h2, l2); split1(x.w, h3, l3);
            size_t base = row * (size_t)KA2 + c;
            *(uint2*)(Y + base)        = make_uint2(pk2(h0, h1), pk2(h2, h3));
            *(uint2*)(Y + base + 1024) = make_uint2(pk2(l0, l1), pk2(l2, l3));
        }
    }
}

// ---------------------------------------------------------------------------
// GEMM core (R8 config): C = A2[*,2048(LUT->3072)] @ W3[*,3072]^T + bias
// 256 threads / 8 warps, warp tile 64x32, bf16 3-term.
// Epilogue modes: 0 fp32 out; 1 q2 fp16 [qh|ql] (scaled); 2 k2 fp16; 3 vh fp16.
// ---------------------------------------------------------------------------
__device__ __forceinline__ int koffA(int it) { return (it < 64 ? it : it - 64) * BK; }

__device__ __forceinline__ void gemm_core(
    const __nv_bfloat16* __restrict__ A, const __nv_bfloat16* __restrict__ W,
    const float* __restrict__ bias, float* __restrict__ Cf,
    __half* __restrict__ OH,
    int mode, float scale, int m0, int n0, char* smem_raw)
{
    const uint32_t sbase = smem_u32(smem_raw);

    const int tid  = threadIdx.x;
    const int lane = tid & 31;
    const int wid  = tid >> 5;
    const int wm   = wid >> 2;
    const int wn   = wid & 3;

    const __nv_bfloat16* Ap = A + (size_t)m0 * KA2;
    const __nv_bfloat16* Wp = W + (size_t)n0 * KSPLIT;

    const int lrow = tid >> 2;
    const int lc   = tid & 3;

    const int arow  = wm * 64 + (lane & 15);
    const int akh   = lane >> 4;
    const int aswz  = (arow >> 1) & 3;
    const int brow  = wn * 32 + (lane & 7) + ((lane & 16) ? 8 : 0);
    const int bkh   = (lane >> 3) & 1;
    const int bswz  = (brow >> 1) & 3;

    float acc[4][4][4];
    #pragma unroll
    for (int i = 0; i < 4; i++)
        #pragma unroll
        for (int j = 0; j < 4; j++)
            #pragma unroll
            for (int k = 0; k < 4; k++) acc[i][j][k] = 0.f;

    #pragma unroll
    for (int s = 0; s < 4; s++) {
        uint32_t sA = sbase + s * 16384;
        uint32_t sB = sA + 8192;
        const __nv_bfloat16* ag = Ap + koffA(s) + lc * 8;
        const __nv_bfloat16* wg = Wp + (size_t)s * BK + lc * 8;
        #pragma unroll
        for (int h = 0; h < 2; h++) {
            int r  = lrow + h * 64;
            int cs = lc ^ ((r >> 1) & 3);
            CP_ASYNC16(sA + r * 64 + cs * 16, ag + (size_t)r * KA2);
            CP_ASYNC16(sB + r * 64 + cs * 16, wg + (size_t)r * KSPLIT);
        }
        if (s & 1) CP_COMMIT();
    }

    int st = 0;
    for (int j = 0; j < NITER / 2; j++) {
        CP_WAIT1();
        __syncthreads();

        #pragma unroll
        for (int half = 0; half < 2; half++) {
            const uint32_t sA = sbase + (st + half) * 16384;
            const uint32_t sB = sA + 8192;
            #pragma unroll
            for (int ks = 0; ks < 2; ks++) {
                uint32_t a[4][4];
                uint32_t b[4][2];
                const int ac = ((ks * 2 + akh) ^ aswz) * 16;
                const int bc = ((ks * 2 + bkh) ^ bswz) * 16;
                #pragma unroll
                for (int mi = 0; mi < 4; mi++)
                    ldsm4(a[mi], sA + (arow + mi * 16) * 64 + ac);
                #pragma unroll
                for (int nj = 0; nj < 2; nj++) {
                    uint32_t t4[4];
                    ldsm4(t4, sB + (brow + nj * 16) * 64 + bc);
                    b[nj * 2][0]     = t4[0]; b[nj * 2][1]     = t4[1];
                    b[nj * 2 + 1][0] = t4[2]; b[nj * 2 + 1][1] = t4[3];
                }
                #pragma unroll
                for (int mi = 0; mi < 4; mi++)
                    #pragma unroll
                    for (int ni = 0; ni < 4; ni++)
                        mma16816(acc[mi][ni], a[mi], b[ni][0], b[ni][1]);
            }
        }

        const int it0 = 2 * j + 4;
        if (it0 < NITER) {
            int pf = st + 4; if (pf >= 6) pf -= 6;
            #pragma unroll
            for (int half = 0; half < 2; half++) {
                const uint32_t dA = sbase + (pf + half) * 16384;
                const uint32_t dB = dA + 8192;
                const __nv_bfloat16* ag = Ap + koffA(it0 + half) + lc * 8;
                const __nv_bfloat16* wg = Wp + (size_t)(it0 + half) * BK + lc * 8;
                #pragma unroll
                for (int h = 0; h < 2; h++) {
                    int r  = lrow + h * 64;
                    int cs = lc ^ ((r >> 1) & 3);
                    CP_ASYNC16(dA + r * 64 + cs * 16, ag + (size_t)r * KA2);
                    CP_ASYNC16(dB + r * 64 + cs * 16, wg + (size_t)r * KSPLIT);
                }
            }
        }
        CP_COMMIT();
        st += 2; if (st >= 6) st -= 6;
    }

    // ---- epilogue ----
    const int trow = lane >> 2;
    const int tcol = (lane & 3) * 2;
    #pragma unroll
    for (int mi = 0; mi < 4; mi++) {
        const int row = m0 + wm * 64 + mi * 16 + trow;
        #pragma unroll
        for (int ni = 0; ni < 4; ni++) {
            const int col = n0 + wn * 32 + ni * 8 + tcol;
            const float b0 = __ldg(bias + col), b1 = __ldg(bias + col + 1);
            float v00 = acc[mi][ni][0] + b0, v01 = acc[mi][ni][1] + b1;
            float v10 = acc[mi][ni][2] + b0, v11 = acc[mi][ni][3] + b1;
            if (mode == 0) {
                *(float2*)(Cf + (size_t)row * EMB + col)       = make_float2(v00, v01);
                *(float2*)(Cf + (size_t)(row + 8) * EMB + col) = make_float2(v10, v11);
            } else {
                v00 *= scale; v01 *= scale; v10 *= scale; v11 *= scale;
                const int hh = col >> 6, d = col & 63;
                const size_t drow = ((size_t)((row >> 11) * NH + hh)) * SEQ + (row & 2047);
                if (mode == 1) {
                    __half h0, h1, h2, h3, l0, l1, l2, l3;
                    split1h(v00, h0, l0); split1h(v01, h1, l1);
                    split1h(v10, h2, l2); split1h(v11, h3, l3);
                    __half* p0 = OH + drow * 128 + d;
                    __half* p1 = OH + (drow + 8) * 128 + d;
                    *(uint32_t*)(p0)      = pk2h(h0, h1);
                    *(uint32_t*)(p0 + 64) = pk2h(l0, l1);
                    *(uint32_t*)(p1)      = pk2h(h2, h3);
                    *(uint32_t*)(p1 + 64) = pk2h(l2, l3);
                } else {
                    *(uint32_t*)(OH + drow * 64 + d) =
                        pk2h(__float2half_rn(v00), __float2half_rn(v01));
                    *(uint32_t*)(OH + (drow + 8) * 64 + d) =
                        pk2h(__float2half_rn(v10), __float2half_rn(v11));
                }
            }
        }
    }
}

// z-batched QKV projections: z=0 -> q2 (scaled), z=1 -> k2, z=2 -> vh
__global__ __launch_bounds__(256, 2)
void gemm_qkv(const __nv_bfloat16* __restrict__ Abase,
              const __nv_bfloat16* __restrict__ Wbase,
              const float* __restrict__ bq, const float* __restrict__ bk,
              const float* __restrict__ bv,
              __half* __restrict__ q2, __half* __restrict__ k2,
              __half* __restrict__ vh)
{
    extern __shared__ __align__(1024) char smem_raw[];
    const int z = blockIdx.z;
    const __nv_bfloat16* A = Abase + (size_t)z * MTOT * KA2;
    const __nv_bfloat16* W = Wbase + (size_t)z * EMB * KSPLIT;
    const float* bias = (z == 0) ? bq : (z == 1) ? bk : bv;
    __half* OH = (z == 0) ? q2 : (z == 1) ? k2 : vh;
    const float scale = (z == 0) ? 0.125f : 1.0f;
    gemm_core(A, W, bias, nullptr, OH, z + 1, scale,
              blockIdx.y * 128, blockIdx.x * 128, smem_raw);
}

// out projection -> fp32 d_out
__global__ __launch_bounds__(256, 2)
void gemm_out(const __nv_bfloat16* __restrict__ A, const __nv_bfloat16* __restrict__ W,
              const float* __restrict__ bias, float* __restrict__ Cf)
{
    extern __shared__ __align__(1024) char smem_raw[];
    gemm_core(A, W, bias, Cf, nullptr, 0, 1.0f,
              blockIdx.y * 128, blockIdx.x * 128, smem_raw);
}

// ---------------------------------------------------------------------------
// HMMA flash attention (causal), fp16:
//   QK: q 2-term [qh|ql] x k 1-term  -> 4 slab-terms (K-fragment reuse)
//   PV: P 2-term (ph+pl) x vh 1-term -> 2 terms
// smem: Q 32KB | K 2x8KB | V 2x8KB = 64KB, occ 2.
// ---------------------------------------------------------------------------
__global__ __launch_bounds__(256, 2)
void attn_hmma(const __half* __restrict__ Q2, const __half* __restrict__ K2,
               const __half* __restrict__ VH, __nv_bfloat16* __restrict__ A2)
{
    extern __shared__ __align__(1024) char smr[];
    const uint32_t sb = smem_u32(smr);
    const uint32_t QS = sb;                 // 4 slabs * 8192B
    const uint32_t KS = sb + 32768;         // 2 stages * 8192 (2 slabs * 4096)
    const uint32_t VS = sb + 49152;         // 2 stages * 8192

    const int tid  = threadIdx.x;
    const int lane = tid & 31;
    const int wid  = tid >> 5;
    const int bx   = gridDim.x - 1 - blockIdx.x;   // LPT: heavy first
    const int head = blockIdx.y;
    const int bz   = blockIdx.z;
    const int qb0  = bx * 128;
    const size_t bh = (size_t)(bz * NH + head);
    const int nkb  = 2 * bx + 2;

    const __half* Qp = Q2 + (bh * SEQ + qb0) * 128;
    const __half* Kp = K2 + bh * SEQ * 64;
    const __half* VHp = VH + bh * SEQ * 64;

    {
        const int r1 = tid >> 2, lc = tid & 3;
        #pragma unroll
        for (int kc = 0; kc < 4; kc++)
            #pragma unroll
            for (int h = 0; h < 2; h++) {
                int r = r1 + h * 64;
                int cs = lc ^ ((r >> 1) & 3);
                CP_ASYNC16(QS + kc * 8192 + r * 64 + cs * 16,
                           Qp + (size_t)r * 128 + kc * 32 + lc * 8);
            }
        int cs = lc ^ ((r1 >> 1) & 3);
        #pragma unroll
        for (int kc = 0; kc < 2; kc++)
            CP_ASYNC16(KS + kc * 4096 + r1 * 64 + cs * 16,
                       Kp + (size_t)r1 * 64 + kc * 32 + lc * 8);
        const int vr = tid >> 3, vc = tid & 7;
        #pragma unroll
        for (int h = 0; h < 2; h++) {
            int r = vr + h * 32;
            int pc = vc ^ (r & 7);
            CP_ASYNC16(VS + r * 128 + pc * 16, VHp + (size_t)r * 64 + vc * 8);
        }
        CP_COMMIT();
    }

    const int arow = wid * 16 + (lane & 15);
    const int akh  = lane >> 4;
    const int aswz = (arow >> 1) & 3;
    const int brow = (lane & 7) + ((lane & 16) ? 8 : 0);
    const int bkh  = (lane >> 3) & 1;
    const int bswz = (brow >> 1) & 3;
    const int vrow = (lane & 7) + 8 * ((lane >> 3) & 1);
    const int vchb = lane >> 4;
    const int vswz = lane & 7;

    float of[8][4];
    #pragma unroll
    for (int i = 0; i < 8; i++)
        #pragma unroll
        for (int j = 0; j < 4; j++) of[i][j] = 0.f;
    float mq[2] = { NEG_BIG, NEG_BIG };
    float lq[2] = { 0.f, 0.f };

    const int qrow0 = qb0 + wid * 16 + (lane >> 2);

    for (int kb = 0; kb < nkb; kb++) {
        const int st = kb & 1;
        const int kbase = kb * 64;

        if (kb + 1 < nkb) {
            const int nb = (kb + 1) * 64;
            const int s2 = st ^ 1;
            const int r1 = tid >> 2, lc = tid & 3;
            int cs = lc ^ ((r1 >> 1) & 3);
            #pragma unroll
            for (int kc = 0; kc < 2; kc++)
                CP_ASYNC16(KS + s2 * 8192 + kc * 4096 + r1 * 64 + cs * 16,
                           Kp + (size_t)(nb + r1) * 64 + kc * 32 + lc * 8);
            const int vr = tid >> 3, vc = tid & 7;
            #pragma unroll
            for (int h = 0; h < 2; h++) {
                int r = vr + h * 32;
                int pc = vc ^ (r & 7);
                CP_ASYNC16(VS + s2 * 8192 + r * 128 + pc * 16,
                           VHp + (size_t)(nb + r) * 64 + vc * 8);
            }
        }
        CP_COMMIT();
        CP_WAIT1();
        __syncthreads();

        // ---- S = (qh+ql).kh^T : 4 slab-terms with K-fragment reuse ----
        float sf[8][4];
        #pragma unroll
        for (int i = 0; i < 8; i++)
            #pragma unroll
            for (int j = 0; j < 4; j++) sf[i][j] = 0.f;

        const uint32_t Kst = KS + st * 8192;
        #pragma unroll
        for (int g = 0; g < 2; g++) {
            #pragma unroll
            for (int ks = 0; ks < 2; ks++) {
                const int bc = ((ks * 2 + bkh) ^ bswz) * 16;
                uint32_t kf[4][4];
                #pragma unroll
                for (int np = 0; np < 4; np++)
                    ldsm4(kf[np], Kst + g * 4096 + (np * 16 + brow) * 64 + bc);
                #pragma unroll
                for (int qi = 0; qi < 2; qi++) {
                    const int qs = g + qi * 2;   // qh slabs {0,1}, ql slabs {2,3}
                    uint32_t a[4];
                    ldsm4(a, QS + qs * 8192 + arow * 64 +
                             (((ks * 2 + akh) ^ aswz) * 16));
                    #pragma unroll
                    for (int np = 0; np < 4; np++) {
                        mma16816h(sf[2 * np],     a, kf[np][0], kf[np][1]);
                        mma16816h(sf[2 * np + 1], a, kf[np][2], kf[np][3]);
                    }
                }
            }
        }

        if (kb >= nkb - 2) {
            #pragma unroll
            for (int nt = 0; nt < 8; nt++) {
                int col = kbase + nt * 8 + 2 * (lane & 3);
                if (col     > qrow0)     sf[nt][0] = NEG_BIG;
                if (col + 1 > qrow0)     sf[nt][1] = NEG_BIG;
                if (col     > qrow0 + 8) sf[nt][2] = NEG_BIG;
                if (col + 1 > qrow0 + 8) sf[nt][3] = NEG_BIG;
            }
        }

        #pragma unroll
        for (int h = 0; h < 2; h++) {
            float mloc = NEG_BIG;
            #pragma unroll
            for (int nt = 0; nt < 8; nt++)
                mloc = fmaxf(mloc, fmaxf(sf[nt][2 * h], sf[nt][2 * h + 1]));
            mloc = fmaxf(mloc, __shfl_xor_sync(0xffffffffu, mloc, 1));
            mloc = fmaxf(mloc, __shfl_xor_sync(0xffffffffu, mloc, 2));
            float mnew = fmaxf(mq[h], mloc);
            float corr = exp2f((mq[h] - mnew) * LOG2E);
            mq[h] = mnew;
            lq[h] *= corr;
            float ps = 0.f;
            #pragma unroll
            for (int nt = 0; nt < 8; nt++) {
                float p0 = exp2f((sf[nt][2 * h] - mnew) * LOG2E);
                float p1 = exp2f((sf[nt][2 * h + 1] - mnew) * LOG2E);
                sf[nt][2 * h] = p0; sf[nt][2 * h + 1] = p1;
                ps += p0 + p1;
                of[nt][2 * h] *= corr; of[nt][2 * h + 1] *= corr;
            }
            ps += __shfl_xor_sync(0xffffffffu, ps, 1);
            ps += __shfl_xor_sync(0xffffffffu, ps, 2);
            lq[h] += ps;
        }

        // ---- O += (ph+pl).vh ----
        const uint32_t Vst = VS + st * 8192;
        #pragma unroll
        for (int kc2 = 0; kc2 < 4; kc2++) {
            const int j0 = 2 * kc2, j1 = j0 + 1;
            uint32_t ph[4], pl[4];
            #pragma unroll
            for (int q = 0; q < 4; q++) {
                const float p0 = (q & 2) ? sf[j1][(q & 1) * 2]     : sf[j0][(q & 1) * 2];
                const float p1 = (q & 2) ? sf[j1][(q & 1) * 2 + 1] : sf[j0][(q & 1) * 2 + 1];
                __half h0, h1, l0, l1;
                split1h(p0, h0, l0); split1h(p1, h1, l1);
                ph[q] = pk2h(h0, h1);
                pl[q] = pk2h(l0, l1);
            }
            const uint32_t rowoff = (kc2 * 16 + vrow) * 128;
            #pragma unroll
            for (int np = 0; np < 4; np++) {
                const int pc = (2 * np + vchb) ^ vswz;
                uint32_t bh4[4];
                ldsm4t(bh4, Vst + rowoff + pc * 16);
                mma16816h(of[2 * np],     ph, bh4[0], bh4[1]);
                mma16816h(of[2 * np + 1], ph, bh4[2], bh4[3]);
                mma16816h(of[2 * np],     pl, bh4[0], bh4[1]);
                mma16816h(of[2 * np + 1], pl, bh4[2], bh4[3]);
            }
        }
        __syncthreads();
    }

    const float inv0 = 1.f / lq[0];
    const float inv1 = 1.f / lq[1];
    const size_t ar0 = (size_t)bz * SEQ + qb0 + wid * 16 + (lane >> 2);
    const size_t ar1 = ar0 + 8;
    const int colb = head * 64 + 2 * (lane & 3);
    #pragma unroll
    for (int nt = 0; nt < 8; nt++) {
        int col = colb + nt * 8;
        float v0 = of[nt][0] * inv0, v1 = of[nt][1] * inv0;
        float v2 = of[nt][2] * inv1, v3 = of[nt][3] * inv1;
        __nv_bfloat16 h0, h1, h2, h3, l0, l1, l2, l3;
        split1(v0, h0, l0); split1(v1, h1, l1);
        split1(v2, h2, l2); split1(v3, h3, l3);
        __nv_bfloat16* d0 = A2 + ar0 * KA2 + col;
        __nv_bfloat16* d1 = A2 + ar1 * KA2 + col;
        *(uint32_t*)(d0)        = pk2(h0, h1);
        *(uint32_t*)(d0 + 1024) = pk2(l0, l1);
        *(uint32_t*)(d1)        = pk2(h2, h3);
        *(uint32_t*)(d1 + 1024) = pk2(l2, l3);
    }
}

// ---------------------------------------------------------------------------
extern "C" void kernel_launch(void* const* d_in, const int* in_sizes, int n_in,
                              void* d_out, int out_size)
{
    const float* query = (const float*)d_in[0];
    const float* key   = (const float*)d_in[1];
    const float* value = (const float*)d_in[2];
    const float* Wq = (const float*)d_in[4];  const float* bq = (const float*)d_in[5];
    const float* Wk = (const float*)d_in[6];  const float* bk = (const float*)d_in[7];
    const float* Wv = (const float*)d_in[8];  const float* bv = (const float*)d_in[9];
    const float* Wo = (const float*)d_in[10]; const float* bo = (const float*)d_in[11];
    float* out = (float*)d_out;

    __nv_bfloat16 *a2p, *w3p;
    __half *q2p, *k2p, *vhp;
    cudaGetSymbolAddress((void**)&a2p, g_a2);
    cudaGetSymbolAddress((void**)&w3p, g_w3);
    cudaGetSymbolAddress((void**)&q2p, g_q2);
    cudaGetSymbolAddress((void**)&k2p, g_k2);
    cudaGetSymbolAddress((void**)&vhp, g_vh);

    const int gsm = 6 * 16384;   // 96KB dynamic
    cudaFuncSetAttribute(gemm_qkv, cudaFuncAttributeMaxDynamicSharedMemorySize, gsm);
    cudaFuncSetAttribute(gemm_out, cudaFuncAttributeMaxDynamicSharedMemorySize, gsm);

    // all splits (4 weights + 3 activations) in one launch
    split_all<<<dim3(1024, 7), 256>>>(query, key, value, Wq, Wk, Wv, Wo, a2p, w3p);

    // QKV projections (z-batched) with fused fp16 per-head epilogues
    gemm_qkv<<<dim3(EMB / 128, MTOT / 128, 3), 256, gsm>>>(
        a2p, w3p, bq, bk, bv, q2p, k2p, vhp);

    // attention -> a2 slot 0 directly
    const int asmem = 65536;
    cudaFuncSetAttribute(attn_hmma, cudaFuncAttributeMaxDynamicSharedMemorySize, asmem);
    attn_hmma<<<dim3(SEQ / 128, NH, BATCH), 256, asmem>>>(q2p, k2p, vhp, a2p);

    // out projection -> d_out
    gemm_out<<<dim3(EMB / 128, MTOT / 128), 256, gsm>>>(
        a2p, w3p + 3 * (size_t)EMB * KSPLIT, bo, out);
}

// round 13
// speedup vs baseline: 1.6943x; 1.2722x over previous
#include <cuda_runtime.h>
#include <cuda_fp16.h>
#include <cstdint>
#include <cstddef>

#define BATCH 4
#define SEQ   2048
#define EMB   1024
#define NH    16
#define HD    64
#define MTOT  (BATCH * SEQ)        /* 8192 */
#define KA2   (2 * EMB)            /* 2048: A-side 2-block [ah|al] fp16 */
#define KW    EMB                  /* 1024: W-side single fp16 block */
#define BK    32
#define NITER (KA2 / BK)           /* 64 */
#define LOG2E 1.44269504f
#define NEG_BIG (-1e30f)
#define BHS   ((size_t)BATCH * NH * SEQ)   /* 131072 per-head rows */

// ---------------- scratch (__device__ globals; no allocs) -------------------
__device__ __align__(1024) __half g_a2[3][(size_t)MTOT * KA2];   // 3x32MB fp16
__device__ __align__(1024) __half g_w1[4][(size_t)EMB * KW];     // 4x2MB fp16
__device__ __align__(1024) __half g_q2[BHS * 128];  // [b,h,s][qh|ql] 32MB
__device__ __align__(1024) __half g_k2[BHS * 64];   // [b,h,s][kh] 16MB
__device__ __align__(1024) __half g_vh[BHS * 64];   // [b,h,s][vh] 16MB

// ---------------- PTX helpers (baseline ISA: sm_80-era ops) -----------------
__device__ __forceinline__ uint32_t smem_u32(const void* p) {
    uint32_t a;
    asm("{ .reg .u64 t; cvta.to.shared.u64 t, %1; cvt.u32.u64 %0, t; }" : "=r"(a) : "l"(p));
    return a;
}
#define CP_ASYNC16(dst, src) \
    asm volatile("cp.async.cg.shared.global [%0], [%1], 16;" :: "r"(dst), "l"(src) : "memory")
#define CP_COMMIT() asm volatile("cp.async.commit_group;" ::: "memory")
#define CP_WAIT1()  asm volatile("cp.async.wait_group 1;" ::: "memory")

__device__ __forceinline__ void ldsm4(uint32_t (&r)[4], uint32_t addr) {
    asm volatile("ldmatrix.sync.aligned.m8n8.x4.shared.b16 {%0,%1,%2,%3}, [%4];"
                 : "=r"(r[0]), "=r"(r[1]), "=r"(r[2]), "=r"(r[3]) : "r"(addr));
}
__device__ __forceinline__ void ldsm4t(uint32_t (&r)[4], uint32_t addr) {
    asm volatile("ldmatrix.sync.aligned.m8n8.x4.trans.shared.b16 {%0,%1,%2,%3}, [%4];"
                 : "=r"(r[0]), "=r"(r[1]), "=r"(r[2]), "=r"(r[3]) : "r"(addr));
}
__device__ __forceinline__ void mma16816h(float (&d)[4], const uint32_t (&a)[4],
                                          uint32_t b0, uint32_t b1) {
    asm volatile(
        "mma.sync.aligned.m16n8k16.row.col.f32.f16.f16.f32 "
        "{%0,%1,%2,%3}, {%4,%5,%6,%7}, {%8,%9}, {%0,%1,%2,%3};"
        : "+f"(d[0]), "+f"(d[1]), "+f"(d[2]), "+f"(d[3])
        : "r"(a[0]), "r"(a[1]), "r"(a[2]), "r"(a[3]), "r"(b0), "r"(b1));
}
__device__ __forceinline__ uint32_t pk2h(__half a, __half b) {
    __half2 t = __halves2half2(a, b);
    return *reinterpret_cast<uint32_t*>(&t);
}
__device__ __forceinline__ void split1h(float v, __half& h, __half& l) {
    h = __float2half_rn(v);
    l = __float2half_rn(v - __half2float(h));
}

// ---------------------------------------------------------------------------
// split_all (one launch): z<4 -> weights single fp16 [wh] (1024-wide);
//                         z>=4 -> activations fp16 [ah|al] (2048-wide)
// ---------------------------------------------------------------------------
__global__ __launch_bounds__(256)
void split_all(const float* __restrict__ q, const float* __restrict__ k,
               const float* __restrict__ v,
               const float* __restrict__ wq, const float* __restrict__ wk,
               const float* __restrict__ wv, const float* __restrict__ wo,
               __half* __restrict__ a2, __half* __restrict__ w1)
{
    const int z = blockIdx.y;
    if (z < 4) {
        const float* X = (z == 0) ? wq : (z == 1) ? wk : (z == 2) ? wv : wo;
        __half* Y = w1 + (size_t)z * EMB * KW;
        size_t idx = (size_t)blockIdx.x * 256 + threadIdx.x;
        float4 x = ((const float4*)X)[idx];
        uint2 hv = make_uint2(pk2h(__float2half_rn(x.x), __float2half_rn(x.y)),
                              pk2h(__float2half_rn(x.z), __float2half_rn(x.w)));
        *(uint2*)(Y + idx * 4) = hv;
    } else {
        const float* X = (z == 4) ? q : (z == 5) ? k : v;
        __half* Y = a2 + (size_t)(z - 4) * MTOT * KA2;
        #pragma unroll
        for (int t = 0; t < 8; t++) {
            size_t idx = ((size_t)blockIdx.x * 8 + t) * 256 + threadIdx.x;
            size_t row = idx >> 8;
            int    c   = (int)(idx & 255) << 2;
            float4 x = ((const float4*)X)[idx];
            __half h0, h1, h2, h3, l0, l1, l2, l3;
            split1h(x.x, h0, l0); split1h(x.y, h1, l1);
            split1h(x.z, h2, l2); split1h(x.w, h3, l3);
            size_t base = row * (size_t)KA2 + c;
            *(uint2*)(Y + base)        = make_uint2(pk2h(h0, h1), pk2h(h2, h3));
            *(uint2*)(Y + base + 1024) = make_uint2(pk2h(l0, l1), pk2h(l2, l3));
        }
    }
}

// ---------------------------------------------------------------------------
// GEMM core: C = (ah+al)[*,2048] @ wh[*,1024 (LUT-repeated)]^T + bias, fp16 MMA.
// 256 threads / 8 warps, warp tile 64x32, 6-stage pipeline, 1 barrier / 2 iters.
// Epilogue modes: 0 fp32 out; 1 q2 fp16 [qh|ql] (scaled); 2 k2 fp16; 3 vh fp16.
// ---------------------------------------------------------------------------
__device__ __forceinline__ int koffW(int it) { return (it < 32 ? it : it - 32) * BK; }

__device__ __forceinline__ void gemm_core(
    const __half* __restrict__ A, const __half* __restrict__ W,
    const float* __restrict__ bias, float* __restrict__ Cf,
    __half* __restrict__ OH,
    int mode, float scale, int m0, int n0, char* smem_raw)
{
    const uint32_t sbase = smem_u32(smem_raw);

    const int tid  = threadIdx.x;
    const int lane = tid & 31;
    const int wid  = tid >> 5;
    const int wm   = wid >> 2;
    const int wn   = wid & 3;

    const __half* Ap = A + (size_t)m0 * KA2;
    const __half* Wp = W + (size_t)n0 * KW;

    const int lrow = tid >> 2;
    const int lc   = tid & 3;

    const int arow  = wm * 64 + (lane & 15);
    const int akh   = lane >> 4;
    const int aswz  = (arow >> 1) & 3;
    const int brow  = wn * 32 + (lane & 7) + ((lane & 16) ? 8 : 0);
    const int bkh   = (lane >> 3) & 1;
    const int bswz  = (brow >> 1) & 3;

    float acc[4][4][4];
    #pragma unroll
    for (int i = 0; i < 4; i++)
        #pragma unroll
        for (int j = 0; j < 4; j++)
            #pragma unroll
            for (int k = 0; k < 4; k++) acc[i][j][k] = 0.f;

    #pragma unroll
    for (int s = 0; s < 4; s++) {
        uint32_t sA = sbase + s * 16384;
        uint32_t sB = sA + 8192;
        const __half* ag = Ap + s * BK + lc * 8;
        const __half* wg = Wp + koffW(s) + lc * 8;
        #pragma unroll
        for (int h = 0; h < 2; h++) {
            int r  = lrow + h * 64;
            int cs = lc ^ ((r >> 1) & 3);
            CP_ASYNC16(sA + r * 64 + cs * 16, ag + (size_t)r * KA2);
            CP_ASYNC16(sB + r * 64 + cs * 16, wg + (size_t)r * KW);
        }
        if (s & 1) CP_COMMIT();
    }

    int st = 0;
    for (int j = 0; j < NITER / 2; j++) {
        CP_WAIT1();
        __syncthreads();

        #pragma unroll
        for (int half = 0; half < 2; half++) {
            const uint32_t sA = sbase + (st + half) * 16384;
            const uint32_t sB = sA + 8192;
            #pragma unroll
            for (int ks = 0; ks < 2; ks++) {
                uint32_t a[4][4];
                uint32_t b[4][2];
                const int ac = ((ks * 2 + akh) ^ aswz) * 16;
                const int bc = ((ks * 2 + bkh) ^ bswz) * 16;
                #pragma unroll
                for (int mi = 0; mi < 4; mi++)
                    ldsm4(a[mi], sA + (arow + mi * 16) * 64 + ac);
                #pragma unroll
                for (int nj = 0; nj < 2; nj++) {
                    uint32_t t4[4];
                    ldsm4(t4, sB + (brow + nj * 16) * 64 + bc);
                    b[nj * 2][0]     = t4[0]; b[nj * 2][1]     = t4[1];
                    b[nj * 2 + 1][0] = t4[2]; b[nj * 2 + 1][1] = t4[3];
                }
                #pragma unroll
                for (int mi = 0; mi < 4; mi++)
                    #pragma unroll
                    for (int ni = 0; ni < 4; ni++)
                        mma16816h(acc[mi][ni], a[mi], b[ni][0], b[ni][1]);
            }
        }

        const int it0 = 2 * j + 4;
        if (it0 < NITER) {
            int pf = st + 4; if (pf >= 6) pf -= 6;
            #pragma unroll
            for (int half = 0; half < 2; half++) {
                const uint32_t dA = sbase + (pf + half) * 16384;
                const uint32_t dB = dA + 8192;
                const __half* ag = Ap + (it0 + half) * BK + lc * 8;
                const __half* wg = Wp + koffW(it0 + half) + lc * 8;
                #pragma unroll
                for (int h = 0; h < 2; h++) {
                    int r  = lrow + h * 64;
                    int cs = lc ^ ((r >> 1) & 3);
                    CP_ASYNC16(dA + r * 64 + cs * 16, ag + (size_t)r * KA2);
                    CP_ASYNC16(dB + r * 64 + cs * 16, wg + (size_t)r * KW);
                }
            }
        }
        CP_COMMIT();
        st += 2; if (st >= 6) st -= 6;
    }

    // ---- epilogue ----
    const int trow = lane >> 2;
    const int tcol = (lane & 3) * 2;
    #pragma unroll
    for (int mi = 0; mi < 4; mi++) {
        const int row = m0 + wm * 64 + mi * 16 + trow;
        #pragma unroll
        for (int ni = 0; ni < 4; ni++) {
            const int col = n0 + wn * 32 + ni * 8 + tcol;
            const float b0 = __ldg(bias + col), b1 = __ldg(bias + col + 1);
            float v00 = acc[mi][ni][0] + b0, v01 = acc[mi][ni][1] + b1;
            float v10 = acc[mi][ni][2] + b0, v11 = acc[mi][ni][3] + b1;
            if (mode == 0) {
                *(float2*)(Cf + (size_t)row * EMB + col)       = make_float2(v00, v01);
                *(float2*)(Cf + (size_t)(row + 8) * EMB + col) = make_float2(v10, v11);
            } else {
                v00 *= scale; v01 *= scale; v10 *= scale; v11 *= scale;
                const int hh = col >> 6, d = col & 63;
                const size_t drow = ((size_t)((row >> 11) * NH + hh)) * SEQ + (row & 2047);
                if (mode == 1) {
                    __half h0, h1, h2, h3, l0, l1, l2, l3;
                    split1h(v00, h0, l0); split1h(v01, h1, l1);
                    split1h(v10, h2, l2); split1h(v11, h3, l3);
                    __half* p0 = OH + drow * 128 + d;
                    __half* p1 = OH + (drow + 8) * 128 + d;
                    *(uint32_t*)(p0)      = pk2h(h0, h1);
                    *(uint32_t*)(p0 + 64) = pk2h(l0, l1);
                    *(uint32_t*)(p1)      = pk2h(h2, h3);
                    *(uint32_t*)(p1 + 64) = pk2h(l2, l3);
                } else {
                    *(uint32_t*)(OH + drow * 64 + d) =
                        pk2h(__float2half_rn(v00), __float2half_rn(v01));
                    *(uint32_t*)(OH + (drow + 8) * 64 + d) =
                        pk2h(__float2half_rn(v10), __float2half_rn(v11));
                }
            }
        }
    }
}

// z-batched QKV projections: z=0 -> q2 (scaled), z=1 -> k2, z=2 -> vh
__global__ __launch_bounds__(256, 2)
void gemm_qkv(const __half* __restrict__ Abase, const __half* __restrict__ Wbase,
              const float* __restrict__ bq, const float* __restrict__ bk,
              const float* __restrict__ bv,
              __half* __restrict__ q2, __half* __restrict__ k2,
              __half* __restrict__ vh)
{
    extern __shared__ __align__(1024) char smem_raw[];
    const int z = blockIdx.z;
    const __half* A = Abase + (size_t)z * MTOT * KA2;
    const __half* W = Wbase + (size_t)z * EMB * KW;
    const float* bias = (z == 0) ? bq : (z == 1) ? bk : bv;
    __half* OH = (z == 0) ? q2 : (z == 1) ? k2 : vh;
    const float scale = (z == 0) ? 0.125f : 1.0f;
    gemm_core(A, W, bias, nullptr, OH, z + 1, scale,
              blockIdx.y * 128, blockIdx.x * 128, smem_raw);
}

// out projection -> fp32 d_out
__global__ __launch_bounds__(256, 2)
void gemm_out(const __half* __restrict__ A, const __half* __restrict__ W,
              const float* __restrict__ bias, float* __restrict__ Cf)
{
    extern __shared__ __align__(1024) char smem_raw[];
    gemm_core(A, W, bias, Cf, nullptr, 0, 1.0f,
              blockIdx.y * 128, blockIdx.x * 128, smem_raw);
}

// ---------------------------------------------------------------------------
// HMMA flash attention (causal), fp16 (unchanged from R12); epilogue now
// writes fp16 [ah|al] a2 rows.
// ---------------------------------------------------------------------------
__global__ __launch_bounds__(256, 2)
void attn_hmma(const __half* __restrict__ Q2, const __half* __restrict__ K2,
               const __half* __restrict__ VH, __half* __restrict__ A2)
{
    extern __shared__ __align__(1024) char smr[];
    const uint32_t sb = smem_u32(smr);
    const uint32_t QS = sb;                 // 4 slabs * 8192B
    const uint32_t KS = sb + 32768;         // 2 stages * 8192
    const uint32_t VS = sb + 49152;         // 2 stages * 8192

    const int tid  = threadIdx.x;
    const int lane = tid & 31;
    const int wid  = tid >> 5;
    const int bx   = gridDim.x - 1 - blockIdx.x;   // LPT: heavy first
    const int head = blockIdx.y;
    const int bz   = blockIdx.z;
    const int qb0  = bx * 128;
    const size_t bh = (size_t)(bz * NH + head);
    const int nkb  = 2 * bx + 2;

    const __half* Qp = Q2 + (bh * SEQ + qb0) * 128;
    const __half* Kp = K2 + bh * SEQ * 64;
    const __half* VHp = VH + bh * SEQ * 64;

    {
        const int r1 = tid >> 2, lc = tid & 3;
        #pragma unroll
        for (int kc = 0; kc < 4; kc++)
            #pragma unroll
            for (int h = 0; h < 2; h++) {
                int r = r1 + h * 64;
                int cs = lc ^ ((r >> 1) & 3);
                CP_ASYNC16(QS + kc * 8192 + r * 64 + cs * 16,
                           Qp + (size_t)r * 128 + kc * 32 + lc * 8);
            }
        int cs = lc ^ ((r1 >> 1) & 3);
        #pragma unroll
        for (int kc = 0; kc < 2; kc++)
            CP_ASYNC16(KS + kc * 4096 + r1 * 64 + cs * 16,
                       Kp + (size_t)r1 * 64 + kc * 32 + lc * 8);
        const int vr = tid >> 3, vc = tid & 7;
        #pragma unroll
        for (int h = 0; h < 2; h++) {
            int r = vr + h * 32;
            int pc = vc ^ (r & 7);
            CP_ASYNC16(VS + r * 128 + pc * 16, VHp + (size_t)r * 64 + vc * 8);
        }
        CP_COMMIT();
    }

    const int arow = wid * 16 + (lane & 15);
    const int akh  = lane >> 4;
    const int aswz = (arow >> 1) & 3;
    const int brow = (lane & 7) + ((lane & 16) ? 8 : 0);
    const int bkh  = (lane >> 3) & 1;
    const int bswz = (brow >> 1) & 3;
    const int vrow = (lane & 7) + 8 * ((lane >> 3) & 1);
    const int vchb = lane >> 4;
    const int vswz = lane & 7;

    float of[8][4];
    #pragma unroll
    for (int i = 0; i < 8; i++)
        #pragma unroll
        for (int j = 0; j < 4; j++) of[i][j] = 0.f;
    float mq[2] = { NEG_BIG, NEG_BIG };
    float lq[2] = { 0.f, 0.f };

    const int qrow0 = qb0 + wid * 16 + (lane >> 2);

    for (int kb = 0; kb < nkb; kb++) {
        const int st = kb & 1;
        const int kbase = kb * 64;

        if (kb + 1 < nkb) {
            const int nb = (kb + 1) * 64;
            const int s2 = st ^ 1;
            const int r1 = tid >> 2, lc = tid & 3;
            int cs = lc ^ ((r1 >> 1) & 3);
            #pragma unroll
            for (int kc = 0; kc < 2; kc++)
                CP_ASYNC16(KS + s2 * 8192 + kc * 4096 + r1 * 64 + cs * 16,
                           Kp + (size_t)(nb + r1) * 64 + kc * 32 + lc * 8);
            const int vr = tid >> 3, vc = tid & 7;
            #pragma unroll
            for (int h = 0; h < 2; h++) {
                int r = vr + h * 32;
                int pc = vc ^ (r & 7);
                CP_ASYNC16(VS + s2 * 8192 + r * 128 + pc * 16,
                           VHp + (size_t)(nb + r) * 64 + vc * 8);
            }
        }
        CP_COMMIT();
        CP_WAIT1();
        __syncthreads();

        float sf[8][4];
        #pragma unroll
        for (int i = 0; i < 8; i++)
            #pragma unroll
            for (int j = 0; j < 4; j++) sf[i][j] = 0.f;

        const uint32_t Kst = KS + st * 8192;
        #pragma unroll
        for (int g = 0; g < 2; g++) {
            #pragma unroll
            for (int ks = 0; ks < 2; ks++) {
                const int bc = ((ks * 2 + bkh) ^ bswz) * 16;
                uint32_t kf[4][4];
                #pragma unroll
                for (int np = 0; np < 4; np++)
                    ldsm4(kf[np], Kst + g * 4096 + (np * 16 + brow) * 64 + bc);
                #pragma unroll
                for (int qi = 0; qi < 2; qi++) {
                    const int qs = g + qi * 2;
                    uint32_t a[4];
                    ldsm4(a, QS + qs * 8192 + arow * 64 +
                             (((ks * 2 + akh) ^ aswz) * 16));
                    #pragma unroll
                    for (int np = 0; np < 4; np++) {
                        mma16816h(sf[2 * np],     a, kf[np][0], kf[np][1]);
                        mma16816h(sf[2 * np + 1], a, kf[np][2], kf[np][3]);
                    }
                }
            }
        }

        if (kb >= nkb - 2) {
            #pragma unroll
            for (int nt = 0; nt < 8; nt++) {
                int col = kbase + nt * 8 + 2 * (lane & 3);
                if (col     > qrow0)     sf[nt][0] = NEG_BIG;
                if (col + 1 > qrow0)     sf[nt][1] = NEG_BIG;
                if (col     > qrow0 + 8) sf[nt][2] = NEG_BIG;
                if (col + 1 > qrow0 + 8) sf[nt][3] = NEG_BIG;
            }
        }

        #pragma unroll
        for (int h = 0; h < 2; h++) {
            float mloc = NEG_BIG;
            #pragma unroll
            for (int nt = 0; nt < 8; nt++)
                mloc = fmaxf(mloc, fmaxf(sf[nt][2 * h], sf[nt][2 * h + 1]));
            mloc = fmaxf(mloc, __shfl_xor_sync(0xffffffffu, mloc, 1));
            mloc = fmaxf(mloc, __shfl_xor_sync(0xffffffffu, mloc, 2));
            float mnew = fmaxf(mq[h], mloc);
            float corr = exp2f((mq[h] - mnew) * LOG2E);
            mq[h] = mnew;
            lq[h] *= corr;
            float ps = 0.f;
            #pragma unroll
            for (int nt = 0; nt < 8; nt++) {
                float p0 = exp2f((sf[nt][2 * h] - mnew) * LOG2E);
                float p1 = exp2f((sf[nt][2 * h + 1] - mnew) * LOG2E);
                sf[nt][2 * h] = p0; sf[nt][2 * h + 1] = p1;
                ps += p0 + p1;
                of[nt][2 * h] *= corr; of[nt][2 * h + 1] *= corr;
            }
            ps += __shfl_xor_sync(0xffffffffu, ps, 1);
            ps += __shfl_xor_sync(0xffffffffu, ps, 2);
            lq[h] += ps;
        }

        const uint32_t Vst = VS + st * 8192;
        #pragma unroll
        for (int kc2 = 0; kc2 < 4; kc2++) {
            const int j0 = 2 * kc2, j1 = j0 + 1;
            uint32_t ph[4], pl[4];
            #pragma unroll
            for (int q = 0; q < 4; q++) {
                const float p0 = (q & 2) ? sf[j1][(q & 1) * 2]     : sf[j0][(q & 1) * 2];
                const float p1 = (q & 2) ? sf[j1][(q & 1) * 2 + 1] : sf[j0][(q & 1) * 2 + 1];
                __half h0, h1, l0, l1;
                split1h(p0, h0, l0); split1h(p1, h1, l1);
                ph[q] = pk2h(h0, h1);
                pl[q] = pk2h(l0, l1);
            }
            const uint32_t rowoff = (kc2 * 16 + vrow) * 128;
            #pragma unroll
            for (int np = 0; np < 4; np++) {
                const int pc = (2 * np + vchb) ^ vswz;
                uint32_t bh4[4];
                ldsm4t(bh4, Vst + rowoff + pc * 16);
                mma16816h(of[2 * np],     ph, bh4[0], bh4[1]);
                mma16816h(of[2 * np + 1], ph, bh4[2], bh4[3]);
                mma16816h(of[2 * np],     pl, bh4[0], bh4[1]);
                mma16816h(of[2 * np + 1], pl, bh4[2], bh4[3]);
            }
        }
        __syncthreads();
    }

    const float inv0 = 1.f / lq[0];
    const float inv1 = 1.f / lq[1];
    const size_t ar0 = (size_t)bz * SEQ + qb0 + wid * 16 + (lane >> 2);
    const size_t ar1 = ar0 + 8;
    const int colb = head * 64 + 2 * (lane & 3);
    #pragma unroll
    for (int nt = 0; nt < 8; nt++) {
        int col = colb + nt * 8;
        float v0 = of[nt][0] * inv0, v1 = of[nt][1] * inv0;
        float v2 = of[nt][2] * inv1, v3 = of[nt][3] * inv1;
        __half h0, h1, h2, h3, l0, l1, l2, l3;
        split1h(v0, h0, l0); split1h(v1, h1, l1);
        split1h(v2, h2, l2); split1h(v3, h3, l3);
        __half* d0 = A2 + ar0 * KA2 + col;
        __half* d1 = A2 + ar1 * KA2 + col;
        *(uint32_t*)(d0)        = pk2h(h0, h1);
        *(uint32_t*)(d0 + 1024) = pk2h(l0, l1);
        *(uint32_t*)(d1)        = pk2h(h2, h3);
        *(uint32_t*)(d1 + 1024) = pk2h(l2, l3);
    }
}

// ---------------------------------------------------------------------------
extern "C" void kernel_launch(void* const* d_in, const int* in_sizes, int n_in,
                              void* d_out, int out_size)
{
    const float* query = (const float*)d_in[0];
    const float* key   = (const float*)d_in[1];
    const float* value = (const float*)d_in[2];
    const float* Wq = (const float*)d_in[4];  const float* bq = (const float*)d_in[5];
    const float* Wk = (const float*)d_in[6];  const float* bk = (const float*)d_in[7];
    const float* Wv = (const float*)d_in[8];  const float* bv = (const float*)d_in[9];
    const float* Wo = (const float*)d_in[10]; const float* bo = (const float*)d_in[11];
    float* out = (float*)d_out;

    __half *a2p, *w1p, *q2p, *k2p, *vhp;
    cudaGetSymbolAddress((void**)&a2p, g_a2);
    cudaGetSymbolAddress((void**)&w1p, g_w1);
    cudaGetSymbolAddress((void**)&q2p, g_q2);
    cudaGetSymbolAddress((void**)&k2p, g_k2);
    cudaGetSymbolAddress((void**)&vhp, g_vh);

    const int gsm = 6 * 16384;   // 96KB dynamic
    cudaFuncSetAttribute(gemm_qkv, cudaFuncAttributeMaxDynamicSharedMemorySize, gsm);
    cudaFuncSetAttribute(gemm_out, cudaFuncAttributeMaxDynamicSharedMemorySize, gsm);

    // all splits (4 weights + 3 activations) in one launch
    split_all<<<dim3(1024, 7), 256>>>(query, key, value, Wq, Wk, Wv, Wo, a2p, w1p);

    // QKV projections (z-batched) with fused fp16 per-head epilogues
    gemm_qkv<<<dim3(EMB / 128, MTOT / 128, 3), 256, gsm>>>(
        a2p, w1p, bq, bk, bv, q2p, k2p, vhp);

    // attention -> a2 slot 0 directly
    const int asmem = 65536;
    cudaFuncSetAttribute(attn_hmma, cudaFuncAttributeMaxDynamicSharedMemorySize, asmem);
    attn_hmma<<<dim3(SEQ / 128, NH, BATCH), 256, asmem>>>(q2p, k2p, vhp, a2p);

    // out projection -> d_out
    gemm_out<<<dim3(EMB / 128, MTOT / 128), 256, gsm>>>(
        a2p, w1p + 3 * (size_t)EMB * KW, bo, out);
}

// round 14
// speedup vs baseline: 2.3240x; 1.3717x over previous
#include <cuda_runtime.h>
#include <cuda_fp16.h>
#include <cstdint>
#include <cstddef>

#define BATCH 4
#define SEQ   2048
#define EMB   1024
#define NH    16
#define HD    64
#define MTOT  (BATCH * SEQ)        /* 8192 */
#define KA    EMB                  /* 1024: single fp16 A block */
#define KW    EMB                  /* 1024: single fp16 W block */
#define BK    32
#define NITER (KA / BK)            /* 32 */
#define LOG2E 1.44269504f
#define NEG_BIG (-1e30f)
#define BHS   ((size_t)BATCH * NH * SEQ)   /* 131072 per-head rows */

// ---------------- scratch (__device__ globals; no allocs) -------------------
__device__ __align__(1024) __half g_a2[3][(size_t)MTOT * KA];    // 3x16MB fp16
__device__ __align__(1024) __half g_w1[4][(size_t)EMB * KW];     // 4x2MB fp16
__device__ __align__(1024) __half g_q2[BHS * 128];  // [b,h,s][qh|ql] 32MB
__device__ __align__(1024) __half g_k2[BHS * 64];   // [b,h,s][kh] 16MB
__device__ __align__(1024) __half g_vh[BHS * 64];   // [b,h,s][vh] 16MB

// ---------------- PTX helpers (baseline ISA: sm_80-era ops) -----------------
__device__ __forceinline__ uint32_t smem_u32(const void* p) {
    uint32_t a;
    asm("{ .reg .u64 t; cvta.to.shared.u64 t, %1; cvt.u32.u64 %0, t; }" : "=r"(a) : "l"(p));
    return a;
}
#define CP_ASYNC16(dst, src) \
    asm volatile("cp.async.cg.shared.global [%0], [%1], 16;" :: "r"(dst), "l"(src) : "memory")
#define CP_COMMIT() asm volatile("cp.async.commit_group;" ::: "memory")
#define CP_WAIT1()  asm volatile("cp.async.wait_group 1;" ::: "memory")

__device__ __forceinline__ void ldsm4(uint32_t (&r)[4], uint32_t addr) {
    asm volatile("ldmatrix.sync.aligned.m8n8.x4.shared.b16 {%0,%1,%2,%3}, [%4];"
                 : "=r"(r[0]), "=r"(r[1]), "=r"(r[2]), "=r"(r[3]) : "r"(addr));
}
__device__ __forceinline__ void ldsm4t(uint32_t (&r)[4], uint32_t addr) {
    asm volatile("ldmatrix.sync.aligned.m8n8.x4.trans.shared.b16 {%0,%1,%2,%3}, [%4];"
                 : "=r"(r[0]), "=r"(r[1]), "=r"(r[2]), "=r"(r[3]) : "r"(addr));
}
__device__ __forceinline__ void mma16816h(float (&d)[4], const uint32_t (&a)[4],
                                          uint32_t b0, uint32_t b1) {
    asm volatile(
        "mma.sync.aligned.m16n8k16.row.col.f32.f16.f16.f32 "
        "{%0,%1,%2,%3}, {%4,%5,%6,%7}, {%8,%9}, {%0,%1,%2,%3};"
        : "+f"(d[0]), "+f"(d[1]), "+f"(d[2]), "+f"(d[3])
        : "r"(a[0]), "r"(a[1]), "r"(a[2]), "r"(a[3]), "r"(b0), "r"(b1));
}
__device__ __forceinline__ uint32_t pk2h(__half a, __half b) {
    __half2 t = __halves2half2(a, b);
    return *reinterpret_cast<uint32_t*>(&t);
}
__device__ __forceinline__ void split1h(float v, __half& h, __half& l) {
    h = __float2half_rn(v);
    l = __float2half_rn(v - __half2float(h));
}

// ---------------------------------------------------------------------------
// split_all (one launch): z<4 -> weights single fp16; z>=4 -> activations
// single fp16 (both 1024-wide rows).
// ---------------------------------------------------------------------------
__global__ __launch_bounds__(256)
void split_all(const float* __restrict__ q, const float* __restrict__ k,
               const float* __restrict__ v,
               const float* __restrict__ wq, const float* __restrict__ wk,
               const float* __restrict__ wv, const float* __restrict__ wo,
               __half* __restrict__ a2, __half* __restrict__ w1)
{
    const int z = blockIdx.y;
    if (z < 4) {
        const float* X = (z == 0) ? wq : (z == 1) ? wk : (z == 2) ? wv : wo;
        __half* Y = w1 + (size_t)z * EMB * KW;
        size_t idx = (size_t)blockIdx.x * 256 + threadIdx.x;
        float4 x = ((const float4*)X)[idx];
        *(uint2*)(Y + idx * 4) =
            make_uint2(pk2h(__float2half_rn(x.x), __float2half_rn(x.y)),
                       pk2h(__float2half_rn(x.z), __float2half_rn(x.w)));
    } else {
        const float* X = (z == 4) ? q : (z == 5) ? k : v;
        __half* Y = a2 + (size_t)(z - 4) * MTOT * KA;
        #pragma unroll
        for (int t = 0; t < 8; t++) {
            size_t idx = ((size_t)blockIdx.x * 8 + t) * 256 + threadIdx.x;
            float4 x = ((const float4*)X)[idx];
            *(uint2*)(Y + idx * 4) =
                make_uint2(pk2h(__float2half_rn(x.x), __float2half_rn(x.y)),
                           pk2h(__float2half_rn(x.z), __float2half_rn(x.w)));
        }
    }
}

// ---------------------------------------------------------------------------
// GEMM core: C = A[*,1024] @ W[*,1024]^T + bias, fp16 MMA, K=1024.
// 256 threads / 8 warps, warp tile 64x32, 6-stage pipeline, 1 barrier / 2 iters.
// Epilogue modes: 0 fp32 out; 1 q2 fp16 [qh|ql] (scaled); 2 k2 fp16; 3 vh fp16.
// ---------------------------------------------------------------------------
__device__ __forceinline__ void gemm_core(
    const __half* __restrict__ A, const __half* __restrict__ W,
    const float* __restrict__ bias, float* __restrict__ Cf,
    __half* __restrict__ OH,
    int mode, float scale, int m0, int n0, char* smem_raw)
{
    const uint32_t sbase = smem_u32(smem_raw);

    const int tid  = threadIdx.x;
    const int lane = tid & 31;
    const int wid  = tid >> 5;
    const int wm   = wid >> 2;
    const int wn   = wid & 3;

    const __half* Ap = A + (size_t)m0 * KA;
    const __half* Wp = W + (size_t)n0 * KW;

    const int lrow = tid >> 2;
    const int lc   = tid & 3;

    const int arow  = wm * 64 + (lane & 15);
    const int akh   = lane >> 4;
    const int aswz  = (arow >> 1) & 3;
    const int brow  = wn * 32 + (lane & 7) + ((lane & 16) ? 8 : 0);
    const int bkh   = (lane >> 3) & 1;
    const int bswz  = (brow >> 1) & 3;

    float acc[4][4][4];
    #pragma unroll
    for (int i = 0; i < 4; i++)
        #pragma unroll
        for (int j = 0; j < 4; j++)
            #pragma unroll
            for (int k = 0; k < 4; k++) acc[i][j][k] = 0.f;

    #pragma unroll
    for (int s = 0; s < 4; s++) {
        uint32_t sA = sbase + s * 16384;
        uint32_t sB = sA + 8192;
        const __half* ag = Ap + s * BK + lc * 8;
        const __half* wg = Wp + s * BK + lc * 8;
        #pragma unroll
        for (int h = 0; h < 2; h++) {
            int r  = lrow + h * 64;
            int cs = lc ^ ((r >> 1) & 3);
            CP_ASYNC16(sA + r * 64 + cs * 16, ag + (size_t)r * KA);
            CP_ASYNC16(sB + r * 64 + cs * 16, wg + (size_t)r * KW);
        }
        if (s & 1) CP_COMMIT();
    }

    int st = 0;
    for (int j = 0; j < NITER / 2; j++) {
        CP_WAIT1();
        __syncthreads();

        #pragma unroll
        for (int half = 0; half < 2; half++) {
            const uint32_t sA = sbase + (st + half) * 16384;
            const uint32_t sB = sA + 8192;
            #pragma unroll
            for (int ks = 0; ks < 2; ks++) {
                uint32_t a[4][4];
                uint32_t b[4][2];
                const int ac = ((ks * 2 + akh) ^ aswz) * 16;
                const int bc = ((ks * 2 + bkh) ^ bswz) * 16;
                #pragma unroll
                for (int mi = 0; mi < 4; mi++)
                    ldsm4(a[mi], sA + (arow + mi * 16) * 64 + ac);
                #pragma unroll
                for (int nj = 0; nj < 2; nj++) {
                    uint32_t t4[4];
                    ldsm4(t4, sB + (brow + nj * 16) * 64 + bc);
                    b[nj * 2][0]     = t4[0]; b[nj * 2][1]     = t4[1];
                    b[nj * 2 + 1][0] = t4[2]; b[nj * 2 + 1][1] = t4[3];
                }
                #pragma unroll
                for (int mi = 0; mi < 4; mi++)
                    #pragma unroll
                    for (int ni = 0; ni < 4; ni++)
                        mma16816h(acc[mi][ni], a[mi], b[ni][0], b[ni][1]);
            }
        }

        const int it0 = 2 * j + 4;
        if (it0 < NITER) {
            int pf = st + 4; if (pf >= 6) pf -= 6;
            #pragma unroll
            for (int half = 0; half < 2; half++) {
                const uint32_t dA = sbase + (pf + half) * 16384;
                const uint32_t dB = dA + 8192;
                const __half* ag = Ap + (it0 + half) * BK + lc * 8;
                const __half* wg = Wp + (it0 + half) * BK + lc * 8;
                #pragma unroll
                for (int h = 0; h < 2; h++) {
                    int r  = lrow + h * 64;
                    int cs = lc ^ ((r >> 1) & 3);
                    CP_ASYNC16(dA + r * 64 + cs * 16, ag + (size_t)r * KA);
                    CP_ASYNC16(dB + r * 64 + cs * 16, wg + (size_t)r * KW);
                }
            }
        }
        CP_COMMIT();
        st += 2; if (st >= 6) st -= 6;
    }

    // ---- epilogue ----
    const int trow = lane >> 2;
    const int tcol = (lane & 3) * 2;
    #pragma unroll
    for (int mi = 0; mi < 4; mi++) {
        const int row = m0 + wm * 64 + mi * 16 + trow;
        #pragma unroll
        for (int ni = 0; ni < 4; ni++) {
            const int col = n0 + wn * 32 + ni * 8 + tcol;
            const float b0 = __ldg(bias + col), b1 = __ldg(bias + col + 1);
            float v00 = acc[mi][ni][0] + b0, v01 = acc[mi][ni][1] + b1;
            float v10 = acc[mi][ni][2] + b0, v11 = acc[mi][ni][3] + b1;
            if (mode == 0) {
                *(float2*)(Cf + (size_t)row * EMB + col)       = make_float2(v00, v01);
                *(float2*)(Cf + (size_t)(row + 8) * EMB + col) = make_float2(v10, v11);
            } else {
                v00 *= scale; v01 *= scale; v10 *= scale; v11 *= scale;
                const int hh = col >> 6, d = col & 63;
                const size_t drow = ((size_t)((row >> 11) * NH + hh)) * SEQ + (row & 2047);
                if (mode == 1) {
                    __half h0, h1, h2, h3, l0, l1, l2, l3;
                    split1h(v00, h0, l0); split1h(v01, h1, l1);
                    split1h(v10, h2, l2); split1h(v11, h3, l3);
                    __half* p0 = OH + drow * 128 + d;
                    __half* p1 = OH + (drow + 8) * 128 + d;
                    *(uint32_t*)(p0)      = pk2h(h0, h1);
                    *(uint32_t*)(p0 + 64) = pk2h(l0, l1);
                    *(uint32_t*)(p1)      = pk2h(h2, h3);
                    *(uint32_t*)(p1 + 64) = pk2h(l2, l3);
                } else {
                    *(uint32_t*)(OH + drow * 64 + d) =
                        pk2h(__float2half_rn(v00), __float2half_rn(v01));
                    *(uint32_t*)(OH + (drow + 8) * 64 + d) =
                        pk2h(__float2half_rn(v10), __float2half_rn(v11));
                }
            }
        }
    }
}

// z-batched QKV projections: z=0 -> q2 (scaled), z=1 -> k2, z=2 -> vh
__global__ __launch_bounds__(256, 2)
void gemm_qkv(const __half* __restrict__ Abase, const __half* __restrict__ Wbase,
              const float* __restrict__ bq, const float* __restrict__ bk,
              const float* __restrict__ bv,
              __half* __restrict__ q2, __half* __restrict__ k2,
              __half* __restrict__ vh)
{
    extern __shared__ __align__(1024) char smem_raw[];
    const int z = blockIdx.z;
    const __half* A = Abase + (size_t)z * MTOT * KA;
    const __half* W = Wbase + (size_t)z * EMB * KW;
    const float* bias = (z == 0) ? bq : (z == 1) ? bk : bv;
    __half* OH = (z == 0) ? q2 : (z == 1) ? k2 : vh;
    const float scale = (z == 0) ? 0.125f : 1.0f;
    gemm_core(A, W, bias, nullptr, OH, z + 1, scale,
              blockIdx.y * 128, blockIdx.x * 128, smem_raw);
}

// out projection -> fp32 d_out
__global__ __launch_bounds__(256, 2)
void gemm_out(const __half* __restrict__ A, const __half* __restrict__ W,
              const float* __restrict__ bias, float* __restrict__ Cf)
{
    extern __shared__ __align__(1024) char smem_raw[];
    gemm_core(A, W, bias, Cf, nullptr, 0, 1.0f,
              blockIdx.y * 128, blockIdx.x * 128, smem_raw);
}

// ---------------------------------------------------------------------------
// HMMA flash attention (causal), fp16 (R12 core); epilogue writes single-fp16
// a2 rows (1024-wide).
// ---------------------------------------------------------------------------
__global__ __launch_bounds__(256, 2)
void attn_hmma(const __half* __restrict__ Q2, const __half* __restrict__ K2,
               const __half* __restrict__ VH, __half* __restrict__ A2)
{
    extern __shared__ __align__(1024) char smr[];
    const uint32_t sb = smem_u32(smr);
    const uint32_t QS = sb;                 // 4 slabs * 8192B
    const uint32_t KS = sb + 32768;         // 2 stages * 8192
    const uint32_t VS = sb + 49152;         // 2 stages * 8192

    const int tid  = threadIdx.x;
    const int lane = tid & 31;
    const int wid  = tid >> 5;
    const int bx   = gridDim.x - 1 - blockIdx.x;   // LPT: heavy first
    const int head = blockIdx.y;
    const int bz   = blockIdx.z;
    const int qb0  = bx * 128;
    const size_t bh = (size_t)(bz * NH + head);
    const int nkb  = 2 * bx + 2;

    const __half* Qp = Q2 + (bh * SEQ + qb0) * 128;
    const __half* Kp = K2 + bh * SEQ * 64;
    const __half* VHp = VH + bh * SEQ * 64;

    {
        const int r1 = tid >> 2, lc = tid & 3;
        #pragma unroll
        for (int kc = 0; kc < 4; kc++)
            #pragma unroll
            for (int h = 0; h < 2; h++) {
                int r = r1 + h * 64;
                int cs = lc ^ ((r >> 1) & 3);
                CP_ASYNC16(QS + kc * 8192 + r * 64 + cs * 16,
                           Qp + (size_t)r * 128 + kc * 32 + lc * 8);
            }
        int cs = lc ^ ((r1 >> 1) & 3);
        #pragma unroll
        for (int kc = 0; kc < 2; kc++)
            CP_ASYNC16(KS + kc * 4096 + r1 * 64 + cs * 16,
                       Kp + (size_t)r1 * 64 + kc * 32 + lc * 8);
        const int vr = tid >> 3, vc = tid & 7;
        #pragma unroll
        for (int h = 0; h < 2; h++) {
            int r = vr + h * 32;
            int pc = vc ^ (r & 7);
            CP_ASYNC16(VS + r * 128 + pc * 16, VHp + (size_t)r * 64 + vc * 8);
        }
        CP_COMMIT();
    }

    const int arow = wid * 16 + (lane & 15);
    const int akh  = lane >> 4;
    const int aswz = (arow >> 1) & 3;
    const int brow = (lane & 7) + ((lane & 16) ? 8 : 0);
    const int bkh  = (lane >> 3) & 1;
    const int bswz = (brow >> 1) & 3;
    const int vrow = (lane & 7) + 8 * ((lane >> 3) & 1);
    const int vchb = lane >> 4;
    const int vswz = lane & 7;

    float of[8][4];
    #pragma unroll
    for (int i = 0; i < 8; i++)
        #pragma unroll
        for (int j = 0; j < 4; j++) of[i][j] = 0.f;
    float mq[2] = { NEG_BIG, NEG_BIG };
    float lq[2] = { 0.f, 0.f };

    const int qrow0 = qb0 + wid * 16 + (lane >> 2);

    for (int kb = 0; kb < nkb; kb++) {
        const int st = kb & 1;
        const int kbase = kb * 64;

        if (kb + 1 < nkb) {
            const int nb = (kb + 1) * 64;
            const int s2 = st ^ 1;
            const int r1 = tid >> 2, lc = tid & 3;
            int cs = lc ^ ((r1 >> 1) & 3);
            #pragma unroll
            for (int kc = 0; kc < 2; kc++)
                CP_ASYNC16(KS + s2 * 8192 + kc * 4096 + r1 * 64 + cs * 16,
                           Kp + (size_t)(nb + r1) * 64 + kc * 32 + lc * 8);
            const int vr = tid >> 3, vc = tid & 7;
            #pragma unroll
            for (int h = 0; h < 2; h++) {
                int r = vr + h * 32;
                int pc = vc ^ (r & 7);
                CP_ASYNC16(VS + s2 * 8192 + r * 128 + pc * 16,
                           VHp + (size_t)(nb + r) * 64 + vc * 8);
            }
        }
        CP_COMMIT();
        CP_WAIT1();
        __syncthreads();

        float sf[8][4];
        #pragma unroll
        for (int i = 0; i < 8; i++)
            #pragma unroll
            for (int j = 0; j < 4; j++) sf[i][j] = 0.f;

        const uint32_t Kst = KS + st * 8192;
        #pragma unroll
        for (int g = 0; g < 2; g++) {
            #pragma unroll
            for (int ks = 0; ks < 2; ks++) {
                const int bc = ((ks * 2 + bkh) ^ bswz) * 16;
                uint32_t kf[4][4];
                #pragma unroll
                for (int np = 0; np < 4; np++)
                    ldsm4(kf[np], Kst + g * 4096 + (np * 16 + brow) * 64 + bc);
                #pragma unroll
                for (int qi = 0; qi < 2; qi++) {
                    const int qs = g + qi * 2;
                    uint32_t a[4];
                    ldsm4(a, QS + qs * 8192 + arow * 64 +
                             (((ks * 2 + akh) ^ aswz) * 16));
                    #pragma unroll
                    for (int np = 0; np < 4; np++) {
                        mma16816h(sf[2 * np],     a, kf[np][0], kf[np][1]);
                        mma16816h(sf[2 * np + 1], a, kf[np][2], kf[np][3]);
                    }
                }
            }
        }

        if (kb >= nkb - 2) {
            #pragma unroll
            for (int nt = 0; nt < 8; nt++) {
                int col = kbase + nt * 8 + 2 * (lane & 3);
                if (col     > qrow0)     sf[nt][0] = NEG_BIG;
                if (col + 1 > qrow0)     sf[nt][1] = NEG_BIG;
                if (col     > qrow0 + 8) sf[nt][2] = NEG_BIG;
                if (col + 1 > qrow0 + 8) sf[nt][3] = NEG_BIG;
            }
        }

        #pragma unroll
        for (int h = 0; h < 2; h++) {
            float mloc = NEG_BIG;
            #pragma unroll
            for (int nt = 0; nt < 8; nt++)
                mloc = fmaxf(mloc, fmaxf(sf[nt][2 * h], sf[nt][2 * h + 1]));
            mloc = fmaxf(mloc, __shfl_xor_sync(0xffffffffu, mloc, 1));
            mloc = fmaxf(mloc, __shfl_xor_sync(0xffffffffu, mloc, 2));
            float mnew = fmaxf(mq[h], mloc);
            float corr = exp2f((mq[h] - mnew) * LOG2E);
            mq[h] = mnew;
            lq[h] *= corr;
            float ps = 0.f;
            #pragma unroll
            for (int nt = 0; nt < 8; nt++) {
                float p0 = exp2f((sf[nt][2 * h] - mnew) * LOG2E);
                float p1 = exp2f((sf[nt][2 * h + 1] - mnew) * LOG2E);
                sf[nt][2 * h] = p0; sf[nt][2 * h + 1] = p1;
                ps += p0 + p1;
                of[nt][2 * h] *= corr; of[nt][2 * h + 1] *= corr;
            }
            ps += __shfl_xor_sync(0xffffffffu, ps, 1);
            ps += __shfl_xor_sync(0xffffffffu, ps, 2);
            lq[h] += ps;
        }

        const uint32_t Vst = VS + st * 8192;
        #pragma unroll
        for (int kc2 = 0; kc2 < 4; kc2++) {
            const int j0 = 2 * kc2, j1 = j0 + 1;
            uint32_t ph[4], pl[4];
            #pragma unroll
            for (int q = 0; q < 4; q++) {
                const float p0 = (q & 2) ? sf[j1][(q & 1) * 2]     : sf[j0][(q & 1) * 2];
                const float p1 = (q & 2) ? sf[j1][(q & 1) * 2 + 1] : sf[j0][(q & 1) * 2 + 1];
                __half h0, h1, l0, l1;
                split1h(p0, h0, l0); split1h(p1, h1, l1);
                ph[q] = pk2h(h0, h1);
                pl[q] = pk2h(l0, l1);
            }
            const uint32_t rowoff = (kc2 * 16 + vrow) * 128;
            #pragma unroll
            for (int np = 0; np < 4; np++) {
                const int pc = (2 * np + vchb) ^ vswz;
                uint32_t bh4[4];
                ldsm4t(bh4, Vst + rowoff + pc * 16);
                mma16816h(of[2 * np],     ph, bh4[0], bh4[1]);
                mma16816h(of[2 * np + 1], ph, bh4[2], bh4[3]);
                mma16816h(of[2 * np],     pl, bh4[0], bh4[1]);
                mma16816h(of[2 * np + 1], pl, bh4[2], bh4[3]);
            }
        }
        __syncthreads();
    }

    const float inv0 = 1.f / lq[0];
    const float inv1 = 1.f / lq[1];
    const size_t ar0 = (size_t)bz * SEQ + qb0 + wid * 16 + (lane >> 2);
    const size_t ar1 = ar0 + 8;
    const int colb = head * 64 + 2 * (lane & 3);
    #pragma unroll
    for (int nt = 0; nt < 8; nt++) {
        int col = colb + nt * 8;
        float v0 = of[nt][0] * inv0, v1 = of[nt][1] * inv0;
        float v2 = of[nt][2] * inv1, v3 = of[nt][3] * inv1;
        *(uint32_t*)(A2 + ar0 * KA + col) =
            pk2h(__float2half_rn(v0), __float2half_rn(v1));
        *(uint32_t*)(A2 + ar1 * KA + col) =
            pk2h(__float2half_rn(v2), __float2half_rn(v3));
    }
}

// ---------------------------------------------------------------------------
extern "C" void kernel_launch(void* const* d_in, const int* in_sizes, int n_in,
                              void* d_out, int out_size)
{
    const float* query = (const float*)d_in[0];
    const float* key   = (const float*)d_in[1];
    const float* value = (const float*)d_in[2];
    const float* Wq = (const float*)d_in[4];  const float* bq = (const float*)d_in[5];
    const float* Wk = (const float*)d_in[6];  const float* bk = (const float*)d_in[7];
    const float* Wv = (const float*)d_in[8];  const float* bv = (const float*)d_in[9];
    const float* Wo = (const float*)d_in[10]; const float* bo = (const float*)d_in[11];
    float* out = (float*)d_out;

    __half *a2p, *w1p, *q2p, *k2p, *vhp;
    cudaGetSymbolAddress((void**)&a2p, g_a2);
    cudaGetSymbolAddress((void**)&w1p, g_w1);
    cudaGetSymbolAddress((void**)&q2p, g_q2);
    cudaGetSymbolAddress((void**)&k2p, g_k2);
    cudaGetSymbolAddress((void**)&vhp, g_vh);

    const int gsm = 6 * 16384;   // 96KB dynamic
    cudaFuncSetAttribute(gemm_qkv, cudaFuncAttributeMaxDynamicSharedMemorySize, gsm);
    cudaFuncSetAttribute(gemm_out, cudaFuncAttributeMaxDynamicSharedMemorySize, gsm);

    // all converts (4 weights + 3 activations) in one launch
    split_all<<<dim3(1024, 7), 256>>>(query, key, value, Wq, Wk, Wv, Wo, a2p, w1p);

    // QKV projections (z-batched) with fused fp16 per-head epilogues
    gemm_qkv<<<dim3(EMB / 128, MTOT / 128, 3), 256, gsm>>>(
        a2p, w1p, bq, bk, bv, q2p, k2p, vhp);

    // attention -> a2 slot 0 directly
    const int asmem = 65536;
    cudaFuncSetAttribute(attn_hmma, cudaFuncAttributeMaxDynamicSharedMemorySize, asmem);
    attn_hmma<<<dim3(SEQ / 128, NH, BATCH), 256, asmem>>>(q2p, k2p, vhp, a2p);

    // out projection -> d_out
    gemm_out<<<dim3(EMB / 128, MTOT / 128), 256, gsm>>>(
        a2p, w1p + 3 * (size_t)EMB * KW, bo, out);
}

// round 15
// speedup vs baseline: 2.8496x; 1.2262x over previous
#include <cuda_runtime.h>
#include <cuda_fp16.h>
#include <cstdint>
#include <cstddef>

#define BATCH 4
#define SEQ   2048
#define EMB   1024
#define NH    16
#define HD    64
#define MTOT  (BATCH * SEQ)        /* 8192 */
#define KA    EMB                  /* 1024: single fp16 A block */
#define KW    EMB                  /* 1024: single fp16 W block */
#define BK    32
#define NITER (KA / BK)            /* 32 */
#define LOG2E 1.44269504f
#define NEG_BIG (-1e30f)
#define BHS   ((size_t)BATCH * NH * SEQ)   /* 131072 per-head rows */

// ---------------- scratch (__device__ globals; no allocs) -------------------
__device__ __align__(1024) __half g_a2[3][(size_t)MTOT * KA];    // 3x16MB fp16
__device__ __align__(1024) __half g_w1[4][(size_t)EMB * KW];     // 4x2MB fp16
__device__ __align__(1024) __half g_q2[BHS * 64];   // [b,h,s][qh] 16MB
__device__ __align__(1024) __half g_k2[BHS * 64];   // [b,h,s][kh] 16MB
__device__ __align__(1024) __half g_vh[BHS * 64];   // [b,h,s][vh] 16MB

// ---------------- PTX helpers (baseline ISA: sm_80-era ops) -----------------
__device__ __forceinline__ uint32_t smem_u32(const void* p) {
    uint32_t a;
    asm("{ .reg .u64 t; cvta.to.shared.u64 t, %1; cvt.u32.u64 %0, t; }" : "=r"(a) : "l"(p));
    return a;
}
#define CP_ASYNC16(dst, src) \
    asm volatile("cp.async.cg.shared.global [%0], [%1], 16;" :: "r"(dst), "l"(src) : "memory")
#define CP_COMMIT() asm volatile("cp.async.commit_group;" ::: "memory")
#define CP_WAIT1()  asm volatile("cp.async.wait_group 1;" ::: "memory")

__device__ __forceinline__ void ldsm4(uint32_t (&r)[4], uint32_t addr) {
    asm volatile("ldmatrix.sync.aligned.m8n8.x4.shared.b16 {%0,%1,%2,%3}, [%4];"
                 : "=r"(r[0]), "=r"(r[1]), "=r"(r[2]), "=r"(r[3]) : "r"(addr));
}
__device__ __forceinline__ void ldsm4t(uint32_t (&r)[4], uint32_t addr) {
    asm volatile("ldmatrix.sync.aligned.m8n8.x4.trans.shared.b16 {%0,%1,%2,%3}, [%4];"
                 : "=r"(r[0]), "=r"(r[1]), "=r"(r[2]), "=r"(r[3]) : "r"(addr));
}
__device__ __forceinline__ void mma16816h(float (&d)[4], const uint32_t (&a)[4],
                                          uint32_t b0, uint32_t b1) {
    asm volatile(
        "mma.sync.aligned.m16n8k16.row.col.f32.f16.f16.f32 "
        "{%0,%1,%2,%3}, {%4,%5,%6,%7}, {%8,%9}, {%0,%1,%2,%3};"
        : "+f"(d[0]), "+f"(d[1]), "+f"(d[2]), "+f"(d[3])
        : "r"(a[0]), "r"(a[1]), "r"(a[2]), "r"(a[3]), "r"(b0), "r"(b1));
}
__device__ __forceinline__ uint32_t pk2h(__half a, __half b) {
    __half2 t = __halves2half2(a, b);
    return *reinterpret_cast<uint32_t*>(&t);
}

// ---------------------------------------------------------------------------
// split_all (one launch): z<4 -> weights fp16; z>=4 -> activations fp16
// ---------------------------------------------------------------------------
__global__ __launch_bounds__(256)
void split_all(const float* __restrict__ q, const float* __restrict__ k,
               const float* __restrict__ v,
               const float* __restrict__ wq, const float* __restrict__ wk,
               const float* __restrict__ wv, const float* __restrict__ wo,
               __half* __restrict__ a2, __half* __restrict__ w1)
{
    const int z = blockIdx.y;
    if (z < 4) {
        const float* X = (z == 0) ? wq : (z == 1) ? wk : (z == 2) ? wv : wo;
        __half* Y = w1 + (size_t)z * EMB * KW;
        size_t idx = (size_t)blockIdx.x * 256 + threadIdx.x;
        float4 x = ((const float4*)X)[idx];
        *(uint2*)(Y + idx * 4) =
            make_uint2(pk2h(__float2half_rn(x.x), __float2half_rn(x.y)),
                       pk2h(__float2half_rn(x.z), __float2half_rn(x.w)));
    } else {
        const float* X = (z == 4) ? q : (z == 5) ? k : v;
        __half* Y = a2 + (size_t)(z - 4) * MTOT * KA;
        #pragma unroll
        for (int t = 0; t < 8; t++) {
            size_t idx = ((size_t)blockIdx.x * 8 + t) * 256 + threadIdx.x;
            float4 x = ((const float4*)X)[idx];
            *(uint2*)(Y + idx * 4) =
                make_uint2(pk2h(__float2half_rn(x.x), __float2half_rn(x.y)),
                           pk2h(__float2half_rn(x.z), __float2half_rn(x.w)));
        }
    }
}

// ---------------------------------------------------------------------------
// GEMM core: C = A[*,1024] @ W[*,1024]^T + bias, fp16 MMA, K=1024.
// 256 threads / 8 warps, warp tile 64x32, 6-stage pipeline, 1 barrier / 2 iters.
// mode 0: fp32 out; mode 1: per-head fp16 64-wide out (with scale).
// ---------------------------------------------------------------------------
__device__ __forceinline__ void gemm_core(
    const __half* __restrict__ A, const __half* __restrict__ W,
    const float* __restrict__ bias, float* __restrict__ Cf,
    __half* __restrict__ OH,
    int mode, float scale, int m0, int n0, char* smem_raw)
{
    const uint32_t sbase = smem_u32(smem_raw);

    const int tid  = threadIdx.x;
    const int lane = tid & 31;
    const int wid  = tid >> 5;
    const int wm   = wid >> 2;
    const int wn   = wid & 3;

    const __half* Ap = A + (size_t)m0 * KA;
    const __half* Wp = W + (size_t)n0 * KW;

    const int lrow = tid >> 2;
    const int lc   = tid & 3;

    const int arow  = wm * 64 + (lane & 15);
    const int akh   = lane >> 4;
    const int aswz  = (arow >> 1) & 3;
    const int brow  = wn * 32 + (lane & 7) + ((lane & 16) ? 8 : 0);
    const int bkh   = (lane >> 3) & 1;
    const int bswz  = (brow >> 1) & 3;

    float acc[4][4][4];
    #pragma unroll
    for (int i = 0; i < 4; i++)
        #pragma unroll
        for (int j = 0; j < 4; j++)
            #pragma unroll
            for (int k = 0; k < 4; k++) acc[i][j][k] = 0.f;

    #pragma unroll
    for (int s = 0; s < 4; s++) {
        uint32_t sA = sbase + s * 16384;
        uint32_t sB = sA + 8192;
        const __half* ag = Ap + s * BK + lc * 8;
        const __half* wg = Wp + s * BK + lc * 8;
        #pragma unroll
        for (int h = 0; h < 2; h++) {
            int r  = lrow + h * 64;
            int cs = lc ^ ((r >> 1) & 3);
            CP_ASYNC16(sA + r * 64 + cs * 16, ag + (size_t)r * KA);
            CP_ASYNC16(sB + r * 64 + cs * 16, wg + (size_t)r * KW);
        }
        if (s & 1) CP_COMMIT();
    }

    int st = 0;
    for (int j = 0; j < NITER / 2; j++) {
        CP_WAIT1();
        __syncthreads();

        #pragma unroll
        for (int half = 0; half < 2; half++) {
            const uint32_t sA = sbase + (st + half) * 16384;
            const uint32_t sB = sA + 8192;
            #pragma unroll
            for (int ks = 0; ks < 2; ks++) {
                uint32_t a[4][4];
                uint32_t b[4][2];
                const int ac = ((ks * 2 + akh) ^ aswz) * 16;
                const int bc = ((ks * 2 + bkh) ^ bswz) * 16;
                #pragma unroll
                for (int mi = 0; mi < 4; mi++)
                    ldsm4(a[mi], sA + (arow + mi * 16) * 64 + ac);
                #pragma unroll
                for (int nj = 0; nj < 2; nj++) {
                    uint32_t t4[4];
                    ldsm4(t4, sB + (brow + nj * 16) * 64 + bc);
                    b[nj * 2][0]     = t4[0]; b[nj * 2][1]     = t4[1];
                    b[nj * 2 + 1][0] = t4[2]; b[nj * 2 + 1][1] = t4[3];
                }
                #pragma unroll
                for (int mi = 0; mi < 4; mi++)
                    #pragma unroll
                    for (int ni = 0; ni < 4; ni++)
                        mma16816h(acc[mi][ni], a[mi], b[ni][0], b[ni][1]);
            }
        }

        const int it0 = 2 * j + 4;
        if (it0 < NITER) {
            int pf = st + 4; if (pf >= 6) pf -= 6;
            #pragma unroll
            for (int half = 0; half < 2; half++) {
                const uint32_t dA = sbase + (pf + half) * 16384;
                const uint32_t dB = dA + 8192;
                const __half* ag = Ap + (it0 + half) * BK + lc * 8;
                const __half* wg = Wp + (it0 + half) * BK + lc * 8;
                #pragma unroll
                for (int h = 0; h < 2; h++) {
                    int r  = lrow + h * 64;
                    int cs = lc ^ ((r >> 1) & 3);
                    CP_ASYNC16(dA + r * 64 + cs * 16, ag + (size_t)r * KA);
                    CP_ASYNC16(dB + r * 64 + cs * 16, wg + (size_t)r * KW);
                }
            }
        }
        CP_COMMIT();
        st += 2; if (st >= 6) st -= 6;
    }

    // ---- epilogue ----
    const int trow = lane >> 2;
    const int tcol = (lane & 3) * 2;
    #pragma unroll
    for (int mi = 0; mi < 4; mi++) {
        const int row = m0 + wm * 64 + mi * 16 + trow;
        #pragma unroll
        for (int ni = 0; ni < 4; ni++) {
            const int col = n0 + wn * 32 + ni * 8 + tcol;
            const float b0 = __ldg(bias + col), b1 = __ldg(bias + col + 1);
            float v00 = acc[mi][ni][0] + b0, v01 = acc[mi][ni][1] + b1;
            float v10 = acc[mi][ni][2] + b0, v11 = acc[mi][ni][3] + b1;
            if (mode == 0) {
                *(float2*)(Cf + (size_t)row * EMB + col)       = make_float2(v00, v01);
                *(float2*)(Cf + (size_t)(row + 8) * EMB + col) = make_float2(v10, v11);
            } else {
                v00 *= scale; v01 *= scale; v10 *= scale; v11 *= scale;
                const int hh = col >> 6, d = col & 63;
                const size_t drow = ((size_t)((row >> 11) * NH + hh)) * SEQ + (row & 2047);
                *(uint32_t*)(OH + drow * 64 + d) =
                    pk2h(__float2half_rn(v00), __float2half_rn(v01));
                *(uint32_t*)(OH + (drow + 8) * 64 + d) =
                    pk2h(__float2half_rn(v10), __float2half_rn(v11));
            }
        }
    }
}

// z-batched QKV projections: z=0 -> q2 (scaled), z=1 -> k2, z=2 -> vh
__global__ __launch_bounds__(256, 2)
void gemm_qkv(const __half* __restrict__ Abase, const __half* __restrict__ Wbase,
              const float* __restrict__ bq, const float* __restrict__ bk,
              const float* __restrict__ bv,
              __half* __restrict__ q2, __half* __restrict__ k2,
              __half* __restrict__ vh)
{
    extern __shared__ __align__(1024) char smem_raw[];
    const int z = blockIdx.z;
    const __half* A = Abase + (size_t)z * MTOT * KA;
    const __half* W = Wbase + (size_t)z * EMB * KW;
    const float* bias = (z == 0) ? bq : (z == 1) ? bk : bv;
    __half* OH = (z == 0) ? q2 : (z == 1) ? k2 : vh;
    const float scale = (z == 0) ? 0.125f : 1.0f;
    gemm_core(A, W, bias, nullptr, OH, 1, scale,
              blockIdx.y * 128, blockIdx.x * 128, smem_raw);
}

// out projection -> fp32 d_out
__global__ __launch_bounds__(256, 2)
void gemm_out(const __half* __restrict__ A, const __half* __restrict__ W,
              const float* __restrict__ bias, float* __restrict__ Cf)
{
    extern __shared__ __align__(1024) char smem_raw[];
    gemm_core(A, W, bias, Cf, nullptr, 0, 1.0f,
              blockIdx.y * 128, blockIdx.x * 128, smem_raw);
}

// ---------------------------------------------------------------------------
// HMMA flash attention (causal), all single fp16 operands:
//   QK: qh x kh (K=64), PV: P x vh (K=64). fp32 accumulate.
// smem: Q 16KB | K 2x8KB | V 2x8KB = 48KB, occ 2.
// ---------------------------------------------------------------------------
__global__ __launch_bounds__(256, 2)
void attn_hmma(const __half* __restrict__ Q2, const __half* __restrict__ K2,
               const __half* __restrict__ VH, __half* __restrict__ A2)
{
    extern __shared__ __align__(1024) char smr[];
    const uint32_t sb = smem_u32(smr);
    const uint32_t QS = sb;                 // 2 slabs * 8192B
    const uint32_t KS = sb + 16384;         // 2 stages * 8192
    const uint32_t VS = sb + 32768;         // 2 stages * 8192

    const int tid  = threadIdx.x;
    const int lane = tid & 31;
    const int wid  = tid >> 5;
    const int bx   = gridDim.x - 1 - blockIdx.x;   // LPT: heavy first
    const int head = blockIdx.y;
    const int bz   = blockIdx.z;
    const int qb0  = bx * 128;
    const size_t bh = (size_t)(bz * NH + head);
    const int nkb  = 2 * bx + 2;

    const __half* Qp = Q2 + (bh * SEQ + qb0) * 64;
    const __half* Kp = K2 + bh * SEQ * 64;
    const __half* VHp = VH + bh * SEQ * 64;

    {
        const int r1 = tid >> 2, lc = tid & 3;
        #pragma unroll
        for (int kc = 0; kc < 2; kc++)
            #pragma unroll
            for (int h = 0; h < 2; h++) {
                int r = r1 + h * 64;
                int cs = lc ^ ((r >> 1) & 3);
                CP_ASYNC16(QS + kc * 8192 + r * 64 + cs * 16,
                           Qp + (size_t)r * 64 + kc * 32 + lc * 8);
            }
        int cs = lc ^ ((r1 >> 1) & 3);
        #pragma unroll
        for (int kc = 0; kc < 2; kc++)
            CP_ASYNC16(KS + kc * 4096 + r1 * 64 + cs * 16,
                       Kp + (size_t)r1 * 64 + kc * 32 + lc * 8);
        const int vr = tid >> 3, vc = tid & 7;
        #pragma unroll
        for (int h = 0; h < 2; h++) {
            int r = vr + h * 32;
            int pc = vc ^ (r & 7);
            CP_ASYNC16(VS + r * 128 + pc * 16, VHp + (size_t)r * 64 + vc * 8);
        }
        CP_COMMIT();
    }

    const int arow = wid * 16 + (lane & 15);
    const int akh  = lane >> 4;
    const int aswz = (arow >> 1) & 3;
    const int brow = (lane & 7) + ((lane & 16) ? 8 : 0);
    const int bkh  = (lane >> 3) & 1;
    const int bswz = (brow >> 1) & 3;
    const int vrow = (lane & 7) + 8 * ((lane >> 3) & 1);
    const int vchb = lane >> 4;
    const int vswz = lane & 7;

    float of[8][4];
    #pragma unroll
    for (int i = 0; i < 8; i++)
        #pragma unroll
        for (int j = 0; j < 4; j++) of[i][j] = 0.f;
    float mq[2] = { NEG_BIG, NEG_BIG };
    float lq[2] = { 0.f, 0.f };

    const int qrow0 = qb0 + wid * 16 + (lane >> 2);

    for (int kb = 0; kb < nkb; kb++) {
        const int st = kb & 1;
        const int kbase = kb * 64;

        if (kb + 1 < nkb) {
            const int nb = (kb + 1) * 64;
            const int s2 = st ^ 1;
            const int r1 = tid >> 2, lc = tid & 3;
            int cs = lc ^ ((r1 >> 1) & 3);
            #pragma unroll
            for (int kc = 0; kc < 2; kc++)
                CP_ASYNC16(KS + s2 * 8192 + kc * 4096 + r1 * 64 + cs * 16,
                           Kp + (size_t)(nb + r1) * 64 + kc * 32 + lc * 8);
            const int vr = tid >> 3, vc = tid & 7;
            #pragma unroll
            for (int h = 0; h < 2; h++) {
                int r = vr + h * 32;
                int pc = vc ^ (r & 7);
                CP_ASYNC16(VS + s2 * 8192 + r * 128 + pc * 16,
                           VHp + (size_t)(nb + r) * 64 + vc * 8);
            }
        }
        CP_COMMIT();
        CP_WAIT1();
        __syncthreads();

        // ---- S = qh . kh^T (K=64) ----
        float sf[8][4];
        #pragma unroll
        for (int i = 0; i < 8; i++)
            #pragma unroll
            for (int j = 0; j < 4; j++) sf[i][j] = 0.f;

        const uint32_t Kst = KS + st * 8192;
        #pragma unroll
        for (int g = 0; g < 2; g++) {
            #pragma unroll
            for (int ks = 0; ks < 2; ks++) {
                const int bc = ((ks * 2 + bkh) ^ bswz) * 16;
                uint32_t a[4];
                ldsm4(a, QS + g * 8192 + arow * 64 + (((ks * 2 + akh) ^ aswz) * 16));
                #pragma unroll
                for (int np = 0; np < 4; np++) {
                    uint32_t kf[4];
                    ldsm4(kf, Kst + g * 4096 + (np * 16 + brow) * 64 + bc);
                    mma16816h(sf[2 * np],     a, kf[0], kf[1]);
                    mma16816h(sf[2 * np + 1], a, kf[2], kf[3]);
                }
            }
        }

        if (kb >= nkb - 2) {
            #pragma unroll
            for (int nt = 0; nt < 8; nt++) {
                int col = kbase + nt * 8 + 2 * (lane & 3);
                if (col     > qrow0)     sf[nt][0] = NEG_BIG;
                if (col + 1 > qrow0)     sf[nt][1] = NEG_BIG;
                if (col     > qrow0 + 8) sf[nt][2] = NEG_BIG;
                if (col + 1 > qrow0 + 8) sf[nt][3] = NEG_BIG;
            }
        }

        #pragma unroll
        for (int h = 0; h < 2; h++) {
            float mloc = NEG_BIG;
            #pragma unroll
            for (int nt = 0; nt < 8; nt++)
                mloc = fmaxf(mloc, fmaxf(sf[nt][2 * h], sf[nt][2 * h + 1]));
            mloc = fmaxf(mloc, __shfl_xor_sync(0xffffffffu, mloc, 1));
            mloc = fmaxf(mloc, __shfl_xor_sync(0xffffffffu, mloc, 2));
            float mnew = fmaxf(mq[h], mloc);
            float corr = exp2f((mq[h] - mnew) * LOG2E);
            mq[h] = mnew;
            lq[h] *= corr;
            float ps = 0.f;
            #pragma unroll
            for (int nt = 0; nt < 8; nt++) {
                float p0 = exp2f((sf[nt][2 * h] - mnew) * LOG2E);
                float p1 = exp2f((sf[nt][2 * h + 1] - mnew) * LOG2E);
                sf[nt][2 * h] = p0; sf[nt][2 * h + 1] = p1;
                ps += p0 + p1;
                of[nt][2 * h] *= corr; of[nt][2 * h + 1] *= corr;
            }
            ps += __shfl_xor_sync(0xffffffffu, ps, 1);
            ps += __shfl_xor_sync(0xffffffffu, ps, 2);
            lq[h] += ps;
        }

        // ---- O += P . vh (single term) ----
        const uint32_t Vst = VS + st * 8192;
        #pragma unroll
        for (int kc2 = 0; kc2 < 4; kc2++) {
            const int j0 = 2 * kc2, j1 = j0 + 1;
            uint32_t ph[4];
            #pragma unroll
            for (int q = 0; q < 4; q++) {
                const float p0 = (q & 2) ? sf[j1][(q & 1) * 2]     : sf[j0][(q & 1) * 2];
                const float p1 = (q & 2) ? sf[j1][(q & 1) * 2 + 1] : sf[j0][(q & 1) * 2 + 1];
                ph[q] = pk2h(__float2half_rn(p0), __float2half_rn(p1));
            }
            const uint32_t rowoff = (kc2 * 16 + vrow) * 128;
            #pragma unroll
            for (int np = 0; np < 4; np++) {
                const int pc = (2 * np + vchb) ^ vswz;
                uint32_t bh4[4];
                ldsm4t(bh4, Vst + rowoff + pc * 16);
                mma16816h(of[2 * np],     ph, bh4[0], bh4[1]);
                mma16816h(of[2 * np + 1], ph, bh4[2], bh4[3]);
            }
        }
        __syncthreads();
    }

    const float inv0 = 1.f / lq[0];
    const float inv1 = 1.f / lq[1];
    const size_t ar0 = (size_t)bz * SEQ + qb0 + wid * 16 + (lane >> 2);
    const size_t ar1 = ar0 + 8;
    const int colb = head * 64 + 2 * (lane & 3);
    #pragma unroll
    for (int nt = 0; nt < 8; nt++) {
        int col = colb + nt * 8;
        float v0 = of[nt][0] * inv0, v1 = of[nt][1] * inv0;
        float v2 = of[nt][2] * inv1, v3 = of[nt][3] * inv1;
        *(uint32_t*)(A2 + ar0 * KA + col) =
            pk2h(__float2half_rn(v0), __float2half_rn(v1));
        *(uint32_t*)(A2 + ar1 * KA + col) =
            pk2h(__float2half_rn(v2), __float2half_rn(v3));
    }
}

// ---------------------------------------------------------------------------
extern "C" void kernel_launch(void* const* d_in, const int* in_sizes, int n_in,
                              void* d_out, int out_size)
{
    const float* query = (const float*)d_in[0];
    const float* key   = (const float*)d_in[1];
    const float* value = (const float*)d_in[2];
    const float* Wq = (const float*)d_in[4];  const float* bq = (const float*)d_in[5];
    const float* Wk = (const float*)d_in[6];  const float* bk = (const float*)d_in[7];
    const float* Wv = (const float*)d_in[8];  const float* bv = (const float*)d_in[9];
    const float* Wo = (const float*)d_in[10]; const float* bo = (const float*)d_in[11];
    float* out = (float*)d_out;

    __half *a2p, *w1p, *q2p, *k2p, *vhp;
    cudaGetSymbolAddress((void**)&a2p, g_a2);
    cudaGetSymbolAddress((void**)&w1p, g_w1);
    cudaGetSymbolAddress((void**)&q2p, g_q2);
    cudaGetSymbolAddress((void**)&k2p, g_k2);
    cudaGetSymbolAddress((void**)&vhp, g_vh);

    const int gsm = 6 * 16384;   // 96KB dynamic
    cudaFuncSetAttribute(gemm_qkv, cudaFuncAttributeMaxDynamicSharedMemorySize, gsm);
    cudaFuncSetAttribute(gemm_out, cudaFuncAttributeMaxDynamicSharedMemorySize, gsm);

    // all converts (4 weights + 3 activations) in one launch
    split_all<<<dim3(1024, 7), 256>>>(query, key, value, Wq, Wk, Wv, Wo, a2p, w1p);

    // QKV projections (z-batched) with fused fp16 per-head epilogues
    gemm_qkv<<<dim3(EMB / 128, MTOT / 128, 3), 256, gsm>>>(
        a2p, w1p, bq, bk, bv, q2p, k2p, vhp);

    // attention -> a2 slot 0 directly
    const int asmem = 49152;
    cudaFuncSetAttribute(attn_hmma, cudaFuncAttributeMaxDynamicSharedMemorySize, asmem);
    attn_hmma<<<dim3(SEQ / 128, NH, BATCH), 256, asmem>>>(q2p, k2p, vhp, a2p);

    // out projection -> d_out
    gemm_out<<<dim3(EMB / 128, MTOT / 128), 256, gsm>>>(
        a2p, w1p + 3 * (size_t)EMB * KW, bo, out);
}